// round 6
// baseline (speedup 1.0000x reference)
#include <cuda_runtime.h>
#include <cuda_bf16.h>
#include <math.h>
#include <stdint.h>

// Problem constants
#define B_   2
#define S_   4096
#define H_   2048
#define NH_  16
#define D_   128
#define NC_  64          // S_/64
#define M_   (B_*S_)     // 8192
#define KTOT 2048

// ---------------------------------------------------------------------------
// Scratch (device globals -- allocation-free per harness rules)
// ---------------------------------------------------------------------------
__device__ float g_q[(size_t)B_*NH_*S_*D_];     // [bh][s][d]
__device__ float g_k[(size_t)B_*NH_*S_*D_];
__device__ float g_u[(size_t)B_*NH_*S_*D_];
__device__ float g_vraw[(size_t)M_*H_];         // [row][col]
__device__ float g_braw[(size_t)M_*H_];
__device__ float g_o[(size_t)M_*H_];            // attn in [b*S+s][h*D+d] layout
__device__ float g_P[(size_t)B_*NH_*NC_*D_*D_]; // per-chunk outer products -> excl prefix
__device__ __nv_bfloat16 g_xh[(size_t)M_*H_];   // split bf16 activations
__device__ __nv_bfloat16 g_xl[(size_t)M_*H_];
__device__ __nv_bfloat16 g_oh[(size_t)M_*H_];
__device__ __nv_bfloat16 g_ol[(size_t)M_*H_];
__device__ __nv_bfloat16 g_Wth[5ull*H_*H_];     // transposed weights [N][K], hi
__device__ __nv_bfloat16 g_Wtl[5ull*H_*H_];     // lo

// ---------------------------------------------------------------------------
// PTX helpers (baseline sm_80+ only; harness targets plain sm_100)
// ---------------------------------------------------------------------------
__device__ __forceinline__ uint32_t s2u(const void* p) {
    uint32_t a;
    asm("{ .reg .u64 t; cvta.to.shared.u64 t, %1; cvt.u32.u64 %0, t; }"
        : "=r"(a) : "l"(p));
    return a;
}

#define CPA(dst, src) \
    asm volatile("cp.async.cg.shared.global [%0], [%1], 16;" :: "r"(dst), "l"(src))
#define CPA_COMMIT() asm volatile("cp.async.commit_group;" ::: "memory")

__device__ __forceinline__ void ldmA(uint32_t (&a)[4], uint32_t addr) {
    asm volatile("ldmatrix.sync.aligned.m8n8.x4.shared.b16 {%0,%1,%2,%3}, [%4];"
                 : "=r"(a[0]), "=r"(a[1]), "=r"(a[2]), "=r"(a[3]) : "r"(addr));
}
__device__ __forceinline__ void ldmB(uint32_t (&b)[2], uint32_t addr) {
    asm volatile("ldmatrix.sync.aligned.m8n8.x2.shared.b16 {%0,%1}, [%2];"
                 : "=r"(b[0]), "=r"(b[1]) : "r"(addr));
}
__device__ __forceinline__ void mma16816(float (&c)[4], const uint32_t (&a)[4],
                                         const uint32_t (&b)[2]) {
    asm volatile(
        "mma.sync.aligned.m16n8k16.row.col.f32.bf16.bf16.f32 "
        "{%0,%1,%2,%3}, {%4,%5,%6,%7}, {%8,%9}, {%0,%1,%2,%3};"
        : "+f"(c[0]), "+f"(c[1]), "+f"(c[2]), "+f"(c[3])
        : "r"(a[0]), "r"(a[1]), "r"(a[2]), "r"(a[3]), "r"(b[0]), "r"(b[1]));
}

// ---------------------------------------------------------------------------
// bf16 split-precision mma.sync GEMM:
//   C[M,2048] = A @ W;  A = Ahi+Alo (bf16, [m][k]),  W^T = Bhi+Blo ([n][k])
//   3 passes: Ahi*Bhi + Ahi*Blo + Alo*Bhi, fp32 accumulate.
// CTA tile 128x256, 512 threads (16 warps: 4M x 4N, warp tile 32x64), BK=32,
// 3-stage cp.async pipeline, single __syncthreads per K-iter.
// mma order: per ni-pair, pass-major -> same-acc revisit distance 4 (no RAW stall).
// MODE 0: flat row-major C[M,N]; MODE 1: head layout out[((b*NH+h)*S+s)*D+d]
// ---------------------------------------------------------------------------
#define BKC 32
#define KT_ (KTOT / BKC)           // 64 iterations
#define PITCH 80                   // bytes per 32-bf16 row (conflict-free ldmatrix)
#define A_BYTES (128 * PITCH)      // 10240
#define B_BYTES (256 * PITCH)      // 20480
#define STAGE_BYTES (2 * A_BYTES + 2 * B_BYTES)   // 61440
#define GEMM_SMEM (3 * STAGE_BYTES)               // 184320

template<int MODE>
__global__ __launch_bounds__(512) void tcgemm(
    const __nv_bfloat16* __restrict__ Ah, const __nv_bfloat16* __restrict__ Al,
    const __nv_bfloat16* __restrict__ Bh, const __nv_bfloat16* __restrict__ Bl,
    float* __restrict__ C)
{
    extern __shared__ char smem[];
    const uint32_t sbase = s2u(smem);
    const int tid = threadIdx.x;
    const int lane = tid & 31, wid = tid >> 5;
    const int wm = wid >> 2, wn = wid & 3;     // 4 x 4 warp grid
    const int bx = blockIdx.x;   // N tile 0..7 (256 cols)
    const int by = blockIdx.y;   // M tile 0..63 (128 rows)

    const __nv_bfloat16* Aph = Ah + (size_t)(by * 128) * KTOT;
    const __nv_bfloat16* Apl = Al + (size_t)(by * 128) * KTOT;
    const __nv_bfloat16* Bph = Bh + (size_t)(bx * 256) * KTOT;
    const __nv_bfloat16* Bpl = Bl + (size_t)(bx * 256) * KTOT;

    float acc[2][8][4];
#pragma unroll
    for (int mi = 0; mi < 2; mi++)
#pragma unroll
        for (int ni = 0; ni < 8; ni++)
#pragma unroll
            for (int j = 0; j < 4; j++) acc[mi][ni][j] = 0.f;

    // stage loader: A hi/lo 1 chunk each, B hi/lo 2 chunks each, per thread
    auto load_stage = [&](int t) {
        uint32_t sb = sbase + (uint32_t)(t % 3) * STAGE_BYTES;
        const int k0 = t * BKC;
        {   // A: 512 float4 chunks per matrix
            int rr = tid >> 2, c = tid & 3;
            uint32_t so = rr * PITCH + c * 16;
            size_t go = (size_t)rr * KTOT + k0 + c * 8;
            CPA(sb + so,           Aph + go);
            CPA(sb + A_BYTES + so, Apl + go);
        }
#pragma unroll
        for (int i = 0; i < 2; i++) {   // B: 1024 float4 chunks per matrix
            int v = tid + i * 512;
            int rr = v >> 2, c = v & 3;
            uint32_t so = rr * PITCH + c * 16;
            size_t go = (size_t)rr * KTOT + k0 + c * 8;
            CPA(sb + 2 * A_BYTES + so,           Bph + go);
            CPA(sb + 2 * A_BYTES + B_BYTES + so, Bpl + go);
        }
        CPA_COMMIT();
    };

    load_stage(0);
    load_stage(1);

    const int arow = lane & 15, achk = lane >> 4;
    const int brow = lane & 7,  bchk = (lane >> 3) & 1;

    for (int t = 0; t < KT_; t++) {
        if (t + 1 < KT_) asm volatile("cp.async.wait_group 1;" ::: "memory");
        else             asm volatile("cp.async.wait_group 0;" ::: "memory");
        __syncthreads();
        if (t + 2 < KT_) load_stage(t + 2);

        const uint32_t sb = sbase + (uint32_t)(t % 3) * STAGE_BYTES;
        const uint32_t aB = sb, bB = sb + 2 * A_BYTES;
#pragma unroll
        for (int ks = 0; ks < 2; ks++) {
            uint32_t ah[2][4], al[2][4];
#pragma unroll
            for (int mi = 0; mi < 2; mi++) {
                uint32_t ra = aB + (uint32_t)(wm * 32 + mi * 16 + arow) * PITCH
                            + ks * 32 + achk * 16;
                ldmA(ah[mi], ra);
                ldmA(al[mi], ra + A_BYTES);
            }
#pragma unroll
            for (int nn = 0; nn < 4; nn++) {   // ni pairs
                uint32_t bh[2][2], bl[2][2];
#pragma unroll
                for (int q = 0; q < 2; q++) {
                    int ni = nn * 2 + q;
                    uint32_t rb = bB + (uint32_t)(wn * 64 + ni * 8 + brow) * PITCH
                                + ks * 32 + bchk * 16;
                    ldmB(bh[q], rb);
                    ldmB(bl[q], rb + B_BYTES);
                }
                // pass-major order: same-acc revisit distance = 4 mmas
#pragma unroll
                for (int q = 0; q < 2; q++)
#pragma unroll
                    for (int mi = 0; mi < 2; mi++)
                        mma16816(acc[mi][nn * 2 + q], ah[mi], bh[q]);
#pragma unroll
                for (int q = 0; q < 2; q++)
#pragma unroll
                    for (int mi = 0; mi < 2; mi++)
                        mma16816(acc[mi][nn * 2 + q], ah[mi], bl[q]);
#pragma unroll
                for (int q = 0; q < 2; q++)
#pragma unroll
                    for (int mi = 0; mi < 2; mi++)
                        mma16816(acc[mi][nn * 2 + q], al[mi], bh[q]);
            }
        }
    }

    // epilogue
#pragma unroll
    for (int mi = 0; mi < 2; mi++) {
        int r0 = by * 128 + wm * 32 + mi * 16 + (lane >> 2);
#pragma unroll
        for (int ni = 0; ni < 8; ni++) {
            int cc = wn * 64 + ni * 8 + (lane & 3) * 2;   // 0..255
            float2 lo = make_float2(acc[mi][ni][0], acc[mi][ni][1]);
            float2 hi = make_float2(acc[mi][ni][2], acc[mi][ni][3]);
            if (MODE == 0) {
                float* p = C + (size_t)r0 * H_ + bx * 256 + cc;
                *(float2*)p = lo;
                *(float2*)(p + 8 * H_) = hi;
            } else {
                int b = r0 >> 12, s = r0 & (S_ - 1);
                int h = bx * 2 + (cc >> 7);
                int d = cc & 127;
                size_t base = ((size_t)(b * NH_ + h) * S_ + s) * D_ + d;
                *(float2*)(C + base) = lo;
                *(float2*)(C + base + 8 * D_) = hi;
            }
        }
    }
}

// ---------------------------------------------------------------------------
// Split fp32 -> bf16 hi/lo (same layout)
// ---------------------------------------------------------------------------
struct alignas(8) bf4 { __nv_bfloat16 v[4]; };

__global__ __launch_bounds__(256) void split_convert(
    const float* __restrict__ in, __nv_bfloat16* __restrict__ hi,
    __nv_bfloat16* __restrict__ lo)
{
    size_t v = (size_t)blockIdx.x * 256 + threadIdx.x;
    float4 x = *(const float4*)(in + v * 4);
    bf4 h, l;
    float xs[4] = {x.x, x.y, x.z, x.w};
#pragma unroll
    for (int i = 0; i < 4; i++) {
        __nv_bfloat16 hh = __float2bfloat16(xs[i]);
        h.v[i] = hh;
        l.v[i] = __float2bfloat16(xs[i] - __bfloat162float(hh));
    }
    *(bf4*)(hi + v * 4) = h;
    *(bf4*)(lo + v * 4) = l;
}

// ---------------------------------------------------------------------------
// Weight transpose + split: Wt[n][k] = W[k][n] as bf16 hi/lo
// ---------------------------------------------------------------------------
__global__ __launch_bounds__(256) void transpose_split(
    const float* __restrict__ in, __nv_bfloat16* __restrict__ outh,
    __nv_bfloat16* __restrict__ outl)
{
    __shared__ float t[32][33];
    int x = blockIdx.x * 32 + threadIdx.x;
    int y = blockIdx.y * 32 + threadIdx.y;
#pragma unroll
    for (int i = 0; i < 32; i += 8)
        t[threadIdx.y + i][threadIdx.x] = in[(size_t)(y + i) * H_ + x];
    __syncthreads();
    x = blockIdx.y * 32 + threadIdx.x;
    y = blockIdx.x * 32 + threadIdx.y;
#pragma unroll
    for (int i = 0; i < 32; i += 8) {
        float val = t[threadIdx.x][threadIdx.y + i];
        __nv_bfloat16 hh = __float2bfloat16(val);
        outh[(size_t)(y + i) * H_ + x] = hh;
        outl[(size_t)(y + i) * H_ + x] = __float2bfloat16(val - __bfloat162float(hh));
    }
}

// ---------------------------------------------------------------------------
// u = sigmoid(braw) * vraw, written to head layout [bh][s][d]
// ---------------------------------------------------------------------------
__global__ __launch_bounds__(256) void ewise_u(
    const float* __restrict__ vr, const float* __restrict__ br,
    float* __restrict__ u)
{
    int v = blockIdx.x * 256 + threadIdx.x;
    int row = v >> 9;
    int col = (v & 511) * 4;
    float4 vv = *(const float4*)(vr + (size_t)row * H_ + col);
    float4 bb = *(const float4*)(br + (size_t)row * H_ + col);
    float4 r;
    r.x = vv.x / (1.f + expf(-bb.x));
    r.y = vv.y / (1.f + expf(-bb.y));
    r.z = vv.z / (1.f + expf(-bb.z));
    r.w = vv.w / (1.f + expf(-bb.w));
    int b = row >> 12, s = row & (S_ - 1);
    int h = col >> 7, d = col & 127;
    *(float4*)(u + ((size_t)(b * NH_ + h) * S_ + s) * D_ + d) = r;
}

// ---------------------------------------------------------------------------
// Per-chunk local work: att = tril(q k^T), o_intra = att @ u, P = u^T k
// ---------------------------------------------------------------------------
#define STP 132
#define CL_SMEM ((3 * 64 * STP + 64 * 65) * 4)

__global__ __launch_bounds__(256) void chunk_local(
    const float* __restrict__ q, const float* __restrict__ k,
    const float* __restrict__ u, float* __restrict__ o,
    float* __restrict__ P)
{
    extern __shared__ float sm[];
    float* sq  = sm;
    float* sk  = sm + 64 * STP;
    float* su  = sm + 2 * 64 * STP;
    float* att = sm + 3 * 64 * STP;   // [64][65]

    const int n = blockIdx.x, bh = blockIdx.y;
    const int tid = threadIdx.x;
    const size_t gbase = ((size_t)bh * S_ + n * 64) * D_;

    for (int v = tid; v < 64 * 32; v += 256) {
        int r = v >> 5, c4 = (v & 31) * 4;
        *(float4*)&sq[r * STP + c4] = *(const float4*)(q + gbase + r * 128 + c4);
        *(float4*)&sk[r * STP + c4] = *(const float4*)(k + gbase + r * 128 + c4);
        *(float4*)&su[r * STP + c4] = *(const float4*)(u + gbase + r * 128 + c4);
    }
    __syncthreads();

    {
        int i0 = (tid >> 4) * 4, j0 = (tid & 15) * 4;
        float a[4][4] = {};
        for (int e = 0; e < 128; e += 4) {
            float4 qv[4], kv[4];
#pragma unroll
            for (int r = 0; r < 4; r++) qv[r] = *(const float4*)&sq[(i0 + r) * STP + e];
#pragma unroll
            for (int c = 0; c < 4; c++) kv[c] = *(const float4*)&sk[(j0 + c) * STP + e];
#pragma unroll
            for (int r = 0; r < 4; r++)
#pragma unroll
                for (int c = 0; c < 4; c++)
                    a[r][c] += qv[r].x * kv[c].x + qv[r].y * kv[c].y
                             + qv[r].z * kv[c].z + qv[r].w * kv[c].w;
        }
#pragma unroll
        for (int r = 0; r < 4; r++)
#pragma unroll
            for (int c = 0; c < 4; c++)
                att[(i0 + r) * 65 + (j0 + c)] = (j0 + c <= i0 + r) ? a[r][c] : 0.f;
    }
    __syncthreads();

    {
        int i0 = (tid >> 4) * 4, d0 = (tid & 15) * 8;
        float acc[4][8] = {};
        for (int j = 0; j < 64; j++) {
            float am[4];
#pragma unroll
            for (int r = 0; r < 4; r++) am[r] = att[(i0 + r) * 65 + j];
            float4 u0 = *(const float4*)&su[j * STP + d0];
            float4 u1 = *(const float4*)&su[j * STP + d0 + 4];
            float uu[8] = {u0.x, u0.y, u0.z, u0.w, u1.x, u1.y, u1.z, u1.w};
#pragma unroll
            for (int r = 0; r < 4; r++)
#pragma unroll
                for (int c = 0; c < 8; c++)
                    acc[r][c] += am[r] * uu[c];
        }
        int b = bh >> 4, h = bh & 15;
#pragma unroll
        for (int r = 0; r < 4; r++) {
            float* p = o + (size_t)(b * S_ + n * 64 + i0 + r) * H_ + h * 128 + d0;
            *(float4*)(p)     = make_float4(acc[r][0], acc[r][1], acc[r][2], acc[r][3]);
            *(float4*)(p + 4) = make_float4(acc[r][4], acc[r][5], acc[r][6], acc[r][7]);
        }
    }

    {
        int d0 = (tid >> 4) * 8, e0 = (tid & 15) * 8;
        float acc[8][8] = {};
        for (int i = 0; i < 64; i++) {
            float4 ua = *(const float4*)&su[i * STP + d0];
            float4 ub = *(const float4*)&su[i * STP + d0 + 4];
            float4 ka = *(const float4*)&sk[i * STP + e0];
            float4 kb = *(const float4*)&sk[i * STP + e0 + 4];
            float uu[8] = {ua.x, ua.y, ua.z, ua.w, ub.x, ub.y, ub.z, ub.w};
            float kk[8] = {ka.x, ka.y, ka.z, ka.w, kb.x, kb.y, kb.z, kb.w};
#pragma unroll
            for (int r = 0; r < 8; r++)
#pragma unroll
                for (int c = 0; c < 8; c++)
                    acc[r][c] += uu[r] * kk[c];
        }
        float* Pp = P + ((size_t)bh * NC_ + n) * (D_ * D_);
#pragma unroll
        for (int r = 0; r < 8; r++) {
            float* p = Pp + (size_t)(d0 + r) * 128 + e0;
            *(float4*)(p)     = make_float4(acc[r][0], acc[r][1], acc[r][2], acc[r][3]);
            *(float4*)(p + 4) = make_float4(acc[r][4], acc[r][5], acc[r][6], acc[r][7]);
        }
    }
}

// ---------------------------------------------------------------------------
// Exclusive prefix over chunks of P per (bh); final state -> output tail
// ---------------------------------------------------------------------------
__global__ __launch_bounds__(256) void prefix_state(
    float* __restrict__ P, float* __restrict__ out_state)
{
    int bh = blockIdx.x >> 3;
    int part = blockIdx.x & 7;
    int idx = part * 2048 + threadIdx.x * 8;
    float acc[8] = {0, 0, 0, 0, 0, 0, 0, 0};
    float* base = P + (size_t)bh * NC_ * (D_ * D_) + idx;
    for (int nn = 0; nn < NC_; nn++) {
        float* p = base + (size_t)nn * (D_ * D_);
        float4 p0 = *(float4*)(p);
        float4 p1 = *(float4*)(p + 4);
        *(float4*)(p)     = make_float4(acc[0], acc[1], acc[2], acc[3]);
        *(float4*)(p + 4) = make_float4(acc[4], acc[5], acc[6], acc[7]);
        acc[0] += p0.x; acc[1] += p0.y; acc[2] += p0.z; acc[3] += p0.w;
        acc[4] += p1.x; acc[5] += p1.y; acc[6] += p1.z; acc[7] += p1.w;
    }
    float* q = out_state + (size_t)bh * (D_ * D_) + idx;
    *(float4*)(q)     = make_float4(acc[0], acc[1], acc[2], acc[3]);
    *(float4*)(q + 4) = make_float4(acc[4], acc[5], acc[6], acc[7]);
}

// ---------------------------------------------------------------------------
// Inter-chunk: o[i][d] += sum_e q[i][e] * S_n[d][e]
// ---------------------------------------------------------------------------
#define IN_SMEM ((64 * STP + 128 * STP) * 4)

__global__ __launch_bounds__(256) void inter_chunk(
    const float* __restrict__ q, const float* __restrict__ P,
    float* __restrict__ o)
{
    extern __shared__ float sm[];
    float* sq = sm;
    float* sS = sm + 64 * STP;

    const int n = blockIdx.x, bh = blockIdx.y;
    const int tid = threadIdx.x;
    const size_t qbase = ((size_t)bh * S_ + n * 64) * D_;
    const float* Sp = P + ((size_t)bh * NC_ + n) * (D_ * D_);

    for (int v = tid; v < 64 * 32; v += 256) {
        int r = v >> 5, c4 = (v & 31) * 4;
        *(float4*)&sq[r * STP + c4] = *(const float4*)(q + qbase + r * 128 + c4);
    }
    for (int v = tid; v < 128 * 32; v += 256) {
        int r = v >> 5, c4 = (v & 31) * 4;
        *(float4*)&sS[r * STP + c4] = *(const float4*)(Sp + (size_t)r * 128 + c4);
    }
    __syncthreads();

    int i0 = (tid >> 4) * 4, d0 = (tid & 15) * 8;
    float acc[4][8] = {};
    for (int e = 0; e < 128; e += 4) {
        float4 qv[4];
#pragma unroll
        for (int r = 0; r < 4; r++) qv[r] = *(const float4*)&sq[(i0 + r) * STP + e];
#pragma unroll
        for (int c = 0; c < 8; c++) {
            float4 sv = *(const float4*)&sS[(d0 + c) * STP + e];
#pragma unroll
            for (int r = 0; r < 4; r++)
                acc[r][c] += qv[r].x * sv.x + qv[r].y * sv.y
                           + qv[r].z * sv.z + qv[r].w * sv.w;
        }
    }
    int b = bh >> 4, h = bh & 15;
#pragma unroll
    for (int r = 0; r < 4; r++) {
        float* p = o + (size_t)(b * S_ + n * 64 + i0 + r) * H_ + h * 128 + d0;
        float4 c0 = *(float4*)(p);
        float4 c1 = *(float4*)(p + 4);
        c0.x += acc[r][0]; c0.y += acc[r][1]; c0.z += acc[r][2]; c0.w += acc[r][3];
        c1.x += acc[r][4]; c1.y += acc[r][5]; c1.z += acc[r][6]; c1.w += acc[r][7];
        *(float4*)(p)     = c0;
        *(float4*)(p + 4) = c1;
    }
}

// ---------------------------------------------------------------------------
// Launch
// ---------------------------------------------------------------------------
extern "C" void kernel_launch(void* const* d_in, const int* in_sizes, int n_in,
                              void* d_out, int out_size)
{
    (void)in_sizes; (void)n_in; (void)out_size;
    const float* x  = (const float*)d_in[0];
    const float* Wq = (const float*)d_in[1];
    const float* Wk = (const float*)d_in[2];
    const float* Wv = (const float*)d_in[3];
    const float* Wb = (const float*)d_in[4];
    const float* Wo = (const float*)d_in[5];
    float* out = (float*)d_out;
    float* out_state = out + (size_t)M_ * H_;

    float *pq, *pk, *pu, *pvr, *pbr, *po, *pP;
    __nv_bfloat16 *pxh, *pxl, *poh, *pol, *pWth, *pWtl;
    cudaGetSymbolAddress((void**)&pq,  g_q);
    cudaGetSymbolAddress((void**)&pk,  g_k);
    cudaGetSymbolAddress((void**)&pu,  g_u);
    cudaGetSymbolAddress((void**)&pvr, g_vraw);
    cudaGetSymbolAddress((void**)&pbr, g_braw);
    cudaGetSymbolAddress((void**)&po,  g_o);
    cudaGetSymbolAddress((void**)&pP,  g_P);
    cudaGetSymbolAddress((void**)&pxh, g_xh);
    cudaGetSymbolAddress((void**)&pxl, g_xl);
    cudaGetSymbolAddress((void**)&poh, g_oh);
    cudaGetSymbolAddress((void**)&pol, g_ol);
    cudaGetSymbolAddress((void**)&pWth, g_Wth);
    cudaGetSymbolAddress((void**)&pWtl, g_Wtl);

    cudaFuncSetAttribute(tcgemm<0>, cudaFuncAttributeMaxDynamicSharedMemorySize, GEMM_SMEM);
    cudaFuncSetAttribute(tcgemm<1>, cudaFuncAttributeMaxDynamicSharedMemorySize, GEMM_SMEM);
    cudaFuncSetAttribute(chunk_local, cudaFuncAttributeMaxDynamicSharedMemorySize, CL_SMEM);
    cudaFuncSetAttribute(inter_chunk, cudaFuncAttributeMaxDynamicSharedMemorySize, IN_SMEM);

    const size_t WSZ = (size_t)H_ * H_;
    dim3 tg(H_ / 32, H_ / 32), tb(32, 8);
    transpose_split<<<tg, tb>>>(Wq, pWth + 0 * WSZ, pWtl + 0 * WSZ);
    transpose_split<<<tg, tb>>>(Wk, pWth + 1 * WSZ, pWtl + 1 * WSZ);
    transpose_split<<<tg, tb>>>(Wv, pWth + 2 * WSZ, pWtl + 2 * WSZ);
    transpose_split<<<tg, tb>>>(Wb, pWth + 3 * WSZ, pWtl + 3 * WSZ);
    transpose_split<<<tg, tb>>>(Wo, pWth + 4 * WSZ, pWtl + 4 * WSZ);

    split_convert<<<(M_ * (H_ / 4)) / 256, 256>>>(x, pxh, pxl);

    dim3 gg(H_ / 256, M_ / 128);   // (8, 64)
    tcgemm<1><<<gg, 512, GEMM_SMEM>>>(pxh, pxl, pWth + 0 * WSZ, pWtl + 0 * WSZ, pq);
    tcgemm<1><<<gg, 512, GEMM_SMEM>>>(pxh, pxl, pWth + 1 * WSZ, pWtl + 1 * WSZ, pk);
    tcgemm<0><<<gg, 512, GEMM_SMEM>>>(pxh, pxl, pWth + 2 * WSZ, pWtl + 2 * WSZ, pvr);
    tcgemm<0><<<gg, 512, GEMM_SMEM>>>(pxh, pxl, pWth + 3 * WSZ, pWtl + 3 * WSZ, pbr);

    ewise_u<<<(M_ * H_ / 4) / 256, 256>>>(pvr, pbr, pu);

    dim3 gc(NC_, B_ * NH_);      // (64, 32)
    chunk_local<<<gc, 256, CL_SMEM>>>(pq, pk, pu, po, pP);
    prefix_state<<<B_ * NH_ * 8, 256>>>(pP, out_state);
    inter_chunk<<<gc, 256, IN_SMEM>>>(pq, pP, po);

    split_convert<<<(M_ * (H_ / 4)) / 256, 256>>>(po, poh, pol);
    tcgemm<0><<<gg, 512, GEMM_SMEM>>>(poh, pol, pWth + 4 * WSZ, pWtl + 4 * WSZ, out);
}

// round 7
// speedup vs baseline: 1.1102x; 1.1102x over previous
#include <cuda_runtime.h>
#include <cuda_bf16.h>
#include <math.h>
#include <stdint.h>

// Problem constants
#define B_   2
#define S_   4096
#define H_   2048
#define NH_  16
#define D_   128
#define NC_  64          // S_/64
#define M_   (B_*S_)     // 8192
#define KTOT 2048

// ---------------------------------------------------------------------------
// Scratch (device globals -- allocation-free per harness rules)
// ---------------------------------------------------------------------------
__device__ float g_q[(size_t)B_*NH_*S_*D_];     // [bh][s][d]
__device__ float g_k[(size_t)B_*NH_*S_*D_];
__device__ float g_u[(size_t)B_*NH_*S_*D_];
__device__ float g_vraw[(size_t)M_*H_];         // [row][col]
__device__ float g_braw[(size_t)M_*H_];
__device__ float g_o[(size_t)M_*H_];            // attn in [b*S+s][h*D+d] layout
__device__ float g_P[(size_t)B_*NH_*NC_*D_*D_]; // per-chunk outer products -> excl prefix
__device__ __nv_bfloat16 g_xh[(size_t)M_*H_];   // split bf16 activations
__device__ __nv_bfloat16 g_xl[(size_t)M_*H_];
__device__ __nv_bfloat16 g_oh[(size_t)M_*H_];
__device__ __nv_bfloat16 g_ol[(size_t)M_*H_];
__device__ __nv_bfloat16 g_Wth[5ull*H_*H_];     // transposed weights [N][K], hi
__device__ __nv_bfloat16 g_Wtl[5ull*H_*H_];     // lo

// ---------------------------------------------------------------------------
// PTX helpers (baseline sm_80+ only; harness targets plain sm_100)
// ---------------------------------------------------------------------------
__device__ __forceinline__ uint32_t s2u(const void* p) {
    uint32_t a;
    asm("{ .reg .u64 t; cvta.to.shared.u64 t, %1; cvt.u32.u64 %0, t; }"
        : "=r"(a) : "l"(p));
    return a;
}

#define CPA(dst, src) \
    asm volatile("cp.async.cg.shared.global [%0], [%1], 16;" :: "r"(dst), "l"(src))
#define CPA_COMMIT() asm volatile("cp.async.commit_group;" ::: "memory")

__device__ __forceinline__ void ldmA(uint32_t (&a)[4], uint32_t addr) {
    asm volatile("ldmatrix.sync.aligned.m8n8.x4.shared.b16 {%0,%1,%2,%3}, [%4];"
                 : "=r"(a[0]), "=r"(a[1]), "=r"(a[2]), "=r"(a[3]) : "r"(addr));
}
__device__ __forceinline__ void ldmB(uint32_t (&b)[2], uint32_t addr) {
    asm volatile("ldmatrix.sync.aligned.m8n8.x2.shared.b16 {%0,%1}, [%2];"
                 : "=r"(b[0]), "=r"(b[1]) : "r"(addr));
}
__device__ __forceinline__ void mma16816(float (&c)[4], const uint32_t (&a)[4],
                                         const uint32_t (&b)[2]) {
    asm volatile(
        "mma.sync.aligned.m16n8k16.row.col.f32.bf16.bf16.f32 "
        "{%0,%1,%2,%3}, {%4,%5,%6,%7}, {%8,%9}, {%0,%1,%2,%3};"
        : "+f"(c[0]), "+f"(c[1]), "+f"(c[2]), "+f"(c[3])
        : "r"(a[0]), "r"(a[1]), "r"(a[2]), "r"(a[3]), "r"(b[0]), "r"(b[1]));
}

// ---------------------------------------------------------------------------
// bf16 split-precision mma.sync GEMM core:
//   acc += A @ B^T over K=2048, 3 passes (Ahi*Bhi + Ahi*Blo + Alo*Bhi).
// CTA tile 128x128, 256 threads (8 warps: 4M x 2N, warp tile 32x64), BK=32,
// 2-stage cp.async pipeline (2 CTAs/SM). SMEM rows padded to 80B.
// mma order: ni-pairs, pass-major -> same-acc revisit distance 4 (no RAW stall).
// ---------------------------------------------------------------------------
#define BKC 32
#define KT_ (KTOT / BKC)          // 64 iterations
#define PITCH 80                  // bytes per 32-bf16 row
#define MAT_BYTES (128 * PITCH)   // 10240 per matrix
#define STAGE_BYTES (4 * MAT_BYTES)  // Ah, Al, Bh, Bl
#define GEMM_SMEM (2 * STAGE_BYTES)  // 81920

__device__ __forceinline__ void gemm_core(
    const __nv_bfloat16* __restrict__ Aph, const __nv_bfloat16* __restrict__ Apl,
    const __nv_bfloat16* __restrict__ Bph, const __nv_bfloat16* __restrict__ Bpl,
    uint32_t sbase, int tid, float (&acc)[2][8][4])
{
    const int lane = tid & 31, wid = tid >> 5;
    const int wm = wid >> 1, wn = wid & 1;

    auto load_stage = [&](int k0, int stg) {
        uint32_t sb = sbase + stg * STAGE_BYTES;
#pragma unroll
        for (int i = 0; i < 2; i++) {
            int v = tid + i * 256;
            int r = v >> 2, c = v & 3;
            uint32_t so = r * PITCH + c * 16;
            size_t go = (size_t)r * KTOT + k0 + c * 8;
            CPA(sb + so,                 Aph + go);
            CPA(sb + MAT_BYTES + so,     Apl + go);
            CPA(sb + 2 * MAT_BYTES + so, Bph + go);
            CPA(sb + 3 * MAT_BYTES + so, Bpl + go);
        }
        CPA_COMMIT();
    };

    load_stage(0, 0);

    const int arow = lane & 15, achk = lane >> 4;
    const int brow = lane & 7,  bchk = (lane >> 3) & 1;

    for (int t = 0; t < KT_; t++) {
        if (t + 1 < KT_) load_stage((t + 1) * BKC, (t + 1) & 1);
        if (t + 1 < KT_) asm volatile("cp.async.wait_group 1;" ::: "memory");
        else             asm volatile("cp.async.wait_group 0;" ::: "memory");
        __syncthreads();

        const uint32_t ab = sbase + (t & 1) * STAGE_BYTES;   // A hi
        const uint32_t bb = ab + 2 * MAT_BYTES;               // B hi
#pragma unroll
        for (int ks = 0; ks < 2; ks++) {
            uint32_t ah[2][4], al[2][4];
#pragma unroll
            for (int mi = 0; mi < 2; mi++) {
                uint32_t ra = ab + (uint32_t)(wm * 32 + mi * 16 + arow) * PITCH
                            + ks * 32 + achk * 16;
                ldmA(ah[mi], ra);
                ldmA(al[mi], ra + MAT_BYTES);
            }
#pragma unroll
            for (int nn = 0; nn < 4; nn++) {   // ni pairs
                uint32_t bh[2][2], bl[2][2];
#pragma unroll
                for (int q = 0; q < 2; q++) {
                    int ni = nn * 2 + q;
                    uint32_t rb = bb + (uint32_t)(wn * 64 + ni * 8 + brow) * PITCH
                                + ks * 32 + bchk * 16;
                    ldmB(bh[q], rb);
                    ldmB(bl[q], rb + MAT_BYTES);
                }
                // pass-major: same-acc revisit distance = 4 mmas
#pragma unroll
                for (int q = 0; q < 2; q++)
#pragma unroll
                    for (int mi = 0; mi < 2; mi++)
                        mma16816(acc[mi][nn * 2 + q], ah[mi], bh[q]);
#pragma unroll
                for (int q = 0; q < 2; q++)
#pragma unroll
                    for (int mi = 0; mi < 2; mi++)
                        mma16816(acc[mi][nn * 2 + q], ah[mi], bl[q]);
#pragma unroll
                for (int q = 0; q < 2; q++)
#pragma unroll
                    for (int mi = 0; mi < 2; mi++)
                        mma16816(acc[mi][nn * 2 + q], al[mi], bh[q]);
            }
        }
        __syncthreads();
    }
}

// Fused 4-projection GEMM: z in {0:q, 1:k, 2:v, 3:b}. q,k -> head layout; v,b flat.
__global__ __launch_bounds__(256, 2) void tcgemm_proj(
    const __nv_bfloat16* __restrict__ Ah, const __nv_bfloat16* __restrict__ Al,
    const __nv_bfloat16* __restrict__ Wth, const __nv_bfloat16* __restrict__ Wtl,
    float* __restrict__ Cq, float* __restrict__ Ck,
    float* __restrict__ Cv, float* __restrict__ Cb)
{
    extern __shared__ char smem[];
    const uint32_t sbase = s2u(smem);
    const int tid = threadIdx.x;
    const int lane = tid & 31, wid = tid >> 5;
    const int wm = wid >> 1, wn = wid & 1;
    const int bx = blockIdx.x, by = blockIdx.y, z = blockIdx.z;
    const size_t WSZ = (size_t)H_ * H_;

    float acc[2][8][4];
#pragma unroll
    for (int mi = 0; mi < 2; mi++)
#pragma unroll
        for (int ni = 0; ni < 8; ni++)
#pragma unroll
            for (int j = 0; j < 4; j++) acc[mi][ni][j] = 0.f;

    gemm_core(Ah + (size_t)(by * 128) * KTOT, Al + (size_t)(by * 128) * KTOT,
              Wth + z * WSZ + (size_t)(bx * 128) * KTOT,
              Wtl + z * WSZ + (size_t)(bx * 128) * KTOT,
              sbase, tid, acc);

    float* C = (z == 0) ? Cq : (z == 1) ? Ck : (z == 2) ? Cv : Cb;
    const bool headlay = (z < 2);
#pragma unroll
    for (int mi = 0; mi < 2; mi++) {
        int r0 = by * 128 + wm * 32 + mi * 16 + (lane >> 2);
#pragma unroll
        for (int ni = 0; ni < 8; ni++) {
            int cc = wn * 64 + ni * 8 + (lane & 3) * 2;
            float2 lo = make_float2(acc[mi][ni][0], acc[mi][ni][1]);
            float2 hi = make_float2(acc[mi][ni][2], acc[mi][ni][3]);
            if (!headlay) {
                float* p = C + (size_t)r0 * H_ + bx * 128 + cc;
                *(float2*)p = lo;
                *(float2*)(p + 8 * H_) = hi;
            } else {
                int b = r0 >> 12, s = r0 & (S_ - 1);
                size_t base = ((size_t)(b * NH_ + bx) * S_ + s) * D_ + cc;
                *(float2*)(C + base) = lo;
                *(float2*)(C + base + 8 * D_) = hi;
            }
        }
    }
}

// Single GEMM (output projection), flat row-major C
__global__ __launch_bounds__(256, 2) void tcgemm_out(
    const __nv_bfloat16* __restrict__ Ah, const __nv_bfloat16* __restrict__ Al,
    const __nv_bfloat16* __restrict__ Bh, const __nv_bfloat16* __restrict__ Bl,
    float* __restrict__ C)
{
    extern __shared__ char smem[];
    const uint32_t sbase = s2u(smem);
    const int tid = threadIdx.x;
    const int lane = tid & 31, wid = tid >> 5;
    const int wm = wid >> 1, wn = wid & 1;
    const int bx = blockIdx.x, by = blockIdx.y;

    float acc[2][8][4];
#pragma unroll
    for (int mi = 0; mi < 2; mi++)
#pragma unroll
        for (int ni = 0; ni < 8; ni++)
#pragma unroll
            for (int j = 0; j < 4; j++) acc[mi][ni][j] = 0.f;

    gemm_core(Ah + (size_t)(by * 128) * KTOT, Al + (size_t)(by * 128) * KTOT,
              Bh + (size_t)(bx * 128) * KTOT, Bl + (size_t)(bx * 128) * KTOT,
              sbase, tid, acc);

#pragma unroll
    for (int mi = 0; mi < 2; mi++) {
        int r0 = by * 128 + wm * 32 + mi * 16 + (lane >> 2);
#pragma unroll
        for (int ni = 0; ni < 8; ni++) {
            int cc = wn * 64 + ni * 8 + (lane & 3) * 2;
            float* p = C + (size_t)r0 * H_ + bx * 128 + cc;
            *(float2*)p = make_float2(acc[mi][ni][0], acc[mi][ni][1]);
            *(float2*)(p + 8 * H_) = make_float2(acc[mi][ni][2], acc[mi][ni][3]);
        }
    }
}

// ---------------------------------------------------------------------------
// Split fp32 -> bf16 hi/lo (same layout)
// ---------------------------------------------------------------------------
struct alignas(8) bf4 { __nv_bfloat16 v[4]; };

__global__ __launch_bounds__(256) void split_convert(
    const float* __restrict__ in, __nv_bfloat16* __restrict__ hi,
    __nv_bfloat16* __restrict__ lo)
{
    size_t v = (size_t)blockIdx.x * 256 + threadIdx.x;
    float4 x = *(const float4*)(in + v * 4);
    bf4 h, l;
    float xs[4] = {x.x, x.y, x.z, x.w};
#pragma unroll
    for (int i = 0; i < 4; i++) {
        __nv_bfloat16 hh = __float2bfloat16(xs[i]);
        h.v[i] = hh;
        l.v[i] = __float2bfloat16(xs[i] - __bfloat162float(hh));
    }
    *(bf4*)(hi + v * 4) = h;
    *(bf4*)(lo + v * 4) = l;
}

// ---------------------------------------------------------------------------
// Weight transpose + split: Wt[n][k] = W[k][n] as bf16 hi/lo (all 5 via z)
// ---------------------------------------------------------------------------
__global__ __launch_bounds__(256) void transpose_split(
    const float* __restrict__ in, __nv_bfloat16* __restrict__ outh,
    __nv_bfloat16* __restrict__ outl)
{
    __shared__ float t[32][33];
    int x = blockIdx.x * 32 + threadIdx.x;
    int y = blockIdx.y * 32 + threadIdx.y;
#pragma unroll
    for (int i = 0; i < 32; i += 8)
        t[threadIdx.y + i][threadIdx.x] = in[(size_t)(y + i) * H_ + x];
    __syncthreads();
    x = blockIdx.y * 32 + threadIdx.x;
    y = blockIdx.x * 32 + threadIdx.y;
#pragma unroll
    for (int i = 0; i < 32; i += 8) {
        float val = t[threadIdx.x][threadIdx.y + i];
        __nv_bfloat16 hh = __float2bfloat16(val);
        outh[(size_t)(y + i) * H_ + x] = hh;
        outl[(size_t)(y + i) * H_ + x] = __float2bfloat16(val - __bfloat162float(hh));
    }
}

// ---------------------------------------------------------------------------
// u = sigmoid(braw) * vraw, written to head layout [bh][s][d]
// ---------------------------------------------------------------------------
__global__ __launch_bounds__(256) void ewise_u(
    const float* __restrict__ vr, const float* __restrict__ br,
    float* __restrict__ u)
{
    int v = blockIdx.x * 256 + threadIdx.x;
    int row = v >> 9;
    int col = (v & 511) * 4;
    float4 vv = *(const float4*)(vr + (size_t)row * H_ + col);
    float4 bb = *(const float4*)(br + (size_t)row * H_ + col);
    float4 r;
    r.x = vv.x / (1.f + expf(-bb.x));
    r.y = vv.y / (1.f + expf(-bb.y));
    r.z = vv.z / (1.f + expf(-bb.z));
    r.w = vv.w / (1.f + expf(-bb.w));
    int b = row >> 12, s = row & (S_ - 1);
    int h = col >> 7, d = col & 127;
    *(float4*)(u + ((size_t)(b * NH_ + h) * S_ + s) * D_ + d) = r;
}

// ---------------------------------------------------------------------------
// Per-chunk local work: att = tril(q k^T), o_intra = att @ u, P = u^T k
// ---------------------------------------------------------------------------
#define STP 132
#define CL_SMEM ((3 * 64 * STP + 64 * 65) * 4)

__global__ __launch_bounds__(256) void chunk_local(
    const float* __restrict__ q, const float* __restrict__ k,
    const float* __restrict__ u, float* __restrict__ o,
    float* __restrict__ P)
{
    extern __shared__ float sm[];
    float* sq  = sm;
    float* sk  = sm + 64 * STP;
    float* su  = sm + 2 * 64 * STP;
    float* att = sm + 3 * 64 * STP;   // [64][65]

    const int n = blockIdx.x, bh = blockIdx.y;
    const int tid = threadIdx.x;
    const size_t gbase = ((size_t)bh * S_ + n * 64) * D_;

    for (int v = tid; v < 64 * 32; v += 256) {
        int r = v >> 5, c4 = (v & 31) * 4;
        *(float4*)&sq[r * STP + c4] = *(const float4*)(q + gbase + r * 128 + c4);
        *(float4*)&sk[r * STP + c4] = *(const float4*)(k + gbase + r * 128 + c4);
        *(float4*)&su[r * STP + c4] = *(const float4*)(u + gbase + r * 128 + c4);
    }
    __syncthreads();

    {
        int i0 = (tid >> 4) * 4, j0 = (tid & 15) * 4;
        float a[4][4] = {};
        for (int e = 0; e < 128; e += 4) {
            float4 qv[4], kv[4];
#pragma unroll
            for (int r = 0; r < 4; r++) qv[r] = *(const float4*)&sq[(i0 + r) * STP + e];
#pragma unroll
            for (int c = 0; c < 4; c++) kv[c] = *(const float4*)&sk[(j0 + c) * STP + e];
#pragma unroll
            for (int r = 0; r < 4; r++)
#pragma unroll
                for (int c = 0; c < 4; c++)
                    a[r][c] += qv[r].x * kv[c].x + qv[r].y * kv[c].y
                             + qv[r].z * kv[c].z + qv[r].w * kv[c].w;
        }
#pragma unroll
        for (int r = 0; r < 4; r++)
#pragma unroll
            for (int c = 0; c < 4; c++)
                att[(i0 + r) * 65 + (j0 + c)] = (j0 + c <= i0 + r) ? a[r][c] : 0.f;
    }
    __syncthreads();

    {
        int i0 = (tid >> 4) * 4, d0 = (tid & 15) * 8;
        float acc[4][8] = {};
        for (int j = 0; j < 64; j++) {
            float am[4];
#pragma unroll
            for (int r = 0; r < 4; r++) am[r] = att[(i0 + r) * 65 + j];
            float4 u0 = *(const float4*)&su[j * STP + d0];
            float4 u1 = *(const float4*)&su[j * STP + d0 + 4];
            float uu[8] = {u0.x, u0.y, u0.z, u0.w, u1.x, u1.y, u1.z, u1.w};
#pragma unroll
            for (int r = 0; r < 4; r++)
#pragma unroll
                for (int c = 0; c < 8; c++)
                    acc[r][c] += am[r] * uu[c];
        }
        int b = bh >> 4, h = bh & 15;
#pragma unroll
        for (int r = 0; r < 4; r++) {
            float* p = o + (size_t)(b * S_ + n * 64 + i0 + r) * H_ + h * 128 + d0;
            *(float4*)(p)     = make_float4(acc[r][0], acc[r][1], acc[r][2], acc[r][3]);
            *(float4*)(p + 4) = make_float4(acc[r][4], acc[r][5], acc[r][6], acc[r][7]);
        }
    }

    {
        int d0 = (tid >> 4) * 8, e0 = (tid & 15) * 8;
        float acc[8][8] = {};
        for (int i = 0; i < 64; i++) {
            float4 ua = *(const float4*)&su[i * STP + d0];
            float4 ub = *(const float4*)&su[i * STP + d0 + 4];
            float4 ka = *(const float4*)&sk[i * STP + e0];
            float4 kb = *(const float4*)&sk[i * STP + e0 + 4];
            float uu[8] = {ua.x, ua.y, ua.z, ua.w, ub.x, ub.y, ub.z, ub.w};
            float kk[8] = {ka.x, ka.y, ka.z, ka.w, kb.x, kb.y, kb.z, kb.w};
#pragma unroll
            for (int r = 0; r < 8; r++)
#pragma unroll
                for (int c = 0; c < 8; c++)
                    acc[r][c] += uu[r] * kk[c];
        }
        float* Pp = P + ((size_t)bh * NC_ + n) * (D_ * D_);
#pragma unroll
        for (int r = 0; r < 8; r++) {
            float* p = Pp + (size_t)(d0 + r) * 128 + e0;
            *(float4*)(p)     = make_float4(acc[r][0], acc[r][1], acc[r][2], acc[r][3]);
            *(float4*)(p + 4) = make_float4(acc[r][4], acc[r][5], acc[r][6], acc[r][7]);
        }
    }
}

// ---------------------------------------------------------------------------
// Exclusive prefix over chunks of P per (bh); final state -> output tail
// ---------------------------------------------------------------------------
__global__ __launch_bounds__(256) void prefix_state(
    float* __restrict__ P, float* __restrict__ out_state)
{
    int bh = blockIdx.x >> 3;
    int part = blockIdx.x & 7;
    int idx = part * 2048 + threadIdx.x * 8;
    float acc[8] = {0, 0, 0, 0, 0, 0, 0, 0};
    float* base = P + (size_t)bh * NC_ * (D_ * D_) + idx;
    for (int nn = 0; nn < NC_; nn++) {
        float* p = base + (size_t)nn * (D_ * D_);
        float4 p0 = *(float4*)(p);
        float4 p1 = *(float4*)(p + 4);
        *(float4*)(p)     = make_float4(acc[0], acc[1], acc[2], acc[3]);
        *(float4*)(p + 4) = make_float4(acc[4], acc[5], acc[6], acc[7]);
        acc[0] += p0.x; acc[1] += p0.y; acc[2] += p0.z; acc[3] += p0.w;
        acc[4] += p1.x; acc[5] += p1.y; acc[6] += p1.z; acc[7] += p1.w;
    }
    float* q = out_state + (size_t)bh * (D_ * D_) + idx;
    *(float4*)(q)     = make_float4(acc[0], acc[1], acc[2], acc[3]);
    *(float4*)(q + 4) = make_float4(acc[4], acc[5], acc[6], acc[7]);
}

// ---------------------------------------------------------------------------
// Inter-chunk: o[i][d] += sum_e q[i][e] * S_n[d][e]
// ---------------------------------------------------------------------------
#define IN_SMEM ((64 * STP + 128 * STP) * 4)

__global__ __launch_bounds__(256) void inter_chunk(
    const float* __restrict__ q, const float* __restrict__ P,
    float* __restrict__ o)
{
    extern __shared__ float sm[];
    float* sq = sm;
    float* sS = sm + 64 * STP;

    const int n = blockIdx.x, bh = blockIdx.y;
    const int tid = threadIdx.x;
    const size_t qbase = ((size_t)bh * S_ + n * 64) * D_;
    const float* Sp = P + ((size_t)bh * NC_ + n) * (D_ * D_);

    for (int v = tid; v < 64 * 32; v += 256) {
        int r = v >> 5, c4 = (v & 31) * 4;
        *(float4*)&sq[r * STP + c4] = *(const float4*)(q + qbase + r * 128 + c4);
    }
    for (int v = tid; v < 128 * 32; v += 256) {
        int r = v >> 5, c4 = (v & 31) * 4;
        *(float4*)&sS[r * STP + c4] = *(const float4*)(Sp + (size_t)r * 128 + c4);
    }
    __syncthreads();

    int i0 = (tid >> 4) * 4, d0 = (tid & 15) * 8;
    float acc[4][8] = {};
    for (int e = 0; e < 128; e += 4) {
        float4 qv[4];
#pragma unroll
        for (int r = 0; r < 4; r++) qv[r] = *(const float4*)&sq[(i0 + r) * STP + e];
#pragma unroll
        for (int c = 0; c < 8; c++) {
            float4 sv = *(const float4*)&sS[(d0 + c) * STP + e];
#pragma unroll
            for (int r = 0; r < 4; r++)
                acc[r][c] += qv[r].x * sv.x + qv[r].y * sv.y
                           + qv[r].z * sv.z + qv[r].w * sv.w;
        }
    }
    int b = bh >> 4, h = bh & 15;
#pragma unroll
    for (int r = 0; r < 4; r++) {
        float* p = o + (size_t)(b * S_ + n * 64 + i0 + r) * H_ + h * 128 + d0;
        float4 c0 = *(float4*)(p);
        float4 c1 = *(float4*)(p + 4);
        c0.x += acc[r][0]; c0.y += acc[r][1]; c0.z += acc[r][2]; c0.w += acc[r][3];
        c1.x += acc[r][4]; c1.y += acc[r][5]; c1.z += acc[r][6]; c1.w += acc[r][7];
        *(float4*)(p)     = c0;
        *(float4*)(p + 4) = c1;
    }
}

// ---------------------------------------------------------------------------
// Launch
// ---------------------------------------------------------------------------
extern "C" void kernel_launch(void* const* d_in, const int* in_sizes, int n_in,
                              void* d_out, int out_size)
{
    (void)in_sizes; (void)n_in; (void)out_size;
    const float* x  = (const float*)d_in[0];
    const float* Wq = (const float*)d_in[1];
    const float* Wk = (const float*)d_in[2];
    const float* Wv = (const float*)d_in[3];
    const float* Wb = (const float*)d_in[4];
    const float* Wo = (const float*)d_in[5];
    float* out = (float*)d_out;
    float* out_state = out + (size_t)M_ * H_;

    float *pq, *pk, *pu, *pvr, *pbr, *po, *pP;
    __nv_bfloat16 *pxh, *pxl, *poh, *pol, *pWth, *pWtl;
    cudaGetSymbolAddress((void**)&pq,  g_q);
    cudaGetSymbolAddress((void**)&pk,  g_k);
    cudaGetSymbolAddress((void**)&pu,  g_u);
    cudaGetSymbolAddress((void**)&pvr, g_vraw);
    cudaGetSymbolAddress((void**)&pbr, g_braw);
    cudaGetSymbolAddress((void**)&po,  g_o);
    cudaGetSymbolAddress((void**)&pP,  g_P);
    cudaGetSymbolAddress((void**)&pxh, g_xh);
    cudaGetSymbolAddress((void**)&pxl, g_xl);
    cudaGetSymbolAddress((void**)&poh, g_oh);
    cudaGetSymbolAddress((void**)&pol, g_ol);
    cudaGetSymbolAddress((void**)&pWth, g_Wth);
    cudaGetSymbolAddress((void**)&pWtl, g_Wtl);

    cudaFuncSetAttribute(tcgemm_proj, cudaFuncAttributeMaxDynamicSharedMemorySize, GEMM_SMEM);
    cudaFuncSetAttribute(tcgemm_out,  cudaFuncAttributeMaxDynamicSharedMemorySize, GEMM_SMEM);
    cudaFuncSetAttribute(chunk_local, cudaFuncAttributeMaxDynamicSharedMemorySize, CL_SMEM);
    cudaFuncSetAttribute(inter_chunk, cudaFuncAttributeMaxDynamicSharedMemorySize, IN_SMEM);

    const size_t WSZ = (size_t)H_ * H_;
    dim3 tg(H_ / 32, H_ / 32), tb(32, 8);
    transpose_split<<<tg, tb>>>(Wq, pWth + 0 * WSZ, pWtl + 0 * WSZ);
    transpose_split<<<tg, tb>>>(Wk, pWth + 1 * WSZ, pWtl + 1 * WSZ);
    transpose_split<<<tg, tb>>>(Wv, pWth + 2 * WSZ, pWtl + 2 * WSZ);
    transpose_split<<<tg, tb>>>(Wb, pWth + 3 * WSZ, pWtl + 3 * WSZ);
    transpose_split<<<tg, tb>>>(Wo, pWth + 4 * WSZ, pWtl + 4 * WSZ);

    split_convert<<<(M_ * (H_ / 4)) / 256, 256>>>(x, pxh, pxl);

    dim3 gp(H_ / 128, M_ / 128, 4);   // (16, 64, 4) fused projections
    tcgemm_proj<<<gp, 256, GEMM_SMEM>>>(pxh, pxl, pWth, pWtl, pq, pk, pvr, pbr);

    ewise_u<<<(M_ * H_ / 4) / 256, 256>>>(pvr, pbr, pu);

    dim3 gc(NC_, B_ * NH_);      // (64, 32)
    chunk_local<<<gc, 256, CL_SMEM>>>(pq, pk, pu, po, pP);
    prefix_state<<<B_ * NH_ * 8, 256>>>(pP, out_state);
    inter_chunk<<<gc, 256, IN_SMEM>>>(pq, pP, po);

    split_convert<<<(M_ * (H_ / 4)) / 256, 256>>>(po, poh, pol);
    dim3 go(H_ / 128, M_ / 128);
    tcgemm_out<<<go, 256, GEMM_SMEM>>>(poh, pol, pWth + 4 * WSZ, pWtl + 4 * WSZ, out);
}

// round 8
// speedup vs baseline: 1.3573x; 1.2226x over previous
#include <cuda_runtime.h>
#include <cuda_fp16.h>
#include <math.h>
#include <stdint.h>

// Problem constants
#define B_   2
#define S_   4096
#define H_   2048
#define NH_  16
#define D_   128
#define NC_  64          // S_/64
#define M_   (B_*S_)     // 8192
#define KTOT 2048

// ---------------------------------------------------------------------------
// Scratch (device globals -- allocation-free per harness rules)
// ---------------------------------------------------------------------------
__device__ float g_q[(size_t)B_*NH_*S_*D_];     // [bh][s][d]
__device__ float g_k[(size_t)B_*NH_*S_*D_];
__device__ float g_u[(size_t)B_*NH_*S_*D_];
__device__ float g_vraw[(size_t)M_*H_];         // [row][col]
__device__ float g_braw[(size_t)M_*H_];
__device__ float g_o[(size_t)M_*H_];            // attn in [b*S+s][h*D+d] layout
__device__ float g_P[(size_t)B_*NH_*NC_*D_*D_]; // per-chunk outer products -> excl prefix
__device__ __half g_xh[(size_t)M_*H_];          // fp16 activations (x)
__device__ __half g_oh[(size_t)M_*H_];          // fp16 activations (o)
__device__ __half g_Wth[5ull*H_*H_];            // transposed weights [N][K] * 64, hi
__device__ __half g_Wtl[5ull*H_*H_];            // lo residual

// ---------------------------------------------------------------------------
// PTX helpers (baseline sm_80+ only; harness targets plain sm_100)
// ---------------------------------------------------------------------------
__device__ __forceinline__ uint32_t s2u(const void* p) {
    uint32_t a;
    asm("{ .reg .u64 t; cvta.to.shared.u64 t, %1; cvt.u32.u64 %0, t; }"
        : "=r"(a) : "l"(p));
    return a;
}

#define CPA(dst, src) \
    asm volatile("cp.async.cg.shared.global [%0], [%1], 16;" :: "r"(dst), "l"(src))
#define CPA_COMMIT() asm volatile("cp.async.commit_group;" ::: "memory")

__device__ __forceinline__ void ldmA(uint32_t (&a)[4], uint32_t addr) {
    asm volatile("ldmatrix.sync.aligned.m8n8.x4.shared.b16 {%0,%1,%2,%3}, [%4];"
                 : "=r"(a[0]), "=r"(a[1]), "=r"(a[2]), "=r"(a[3]) : "r"(addr));
}
__device__ __forceinline__ void ldmB(uint32_t (&b)[2], uint32_t addr) {
    asm volatile("ldmatrix.sync.aligned.m8n8.x2.shared.b16 {%0,%1}, [%2];"
                 : "=r"(b[0]), "=r"(b[1]) : "r"(addr));
}
__device__ __forceinline__ void mma16816(float (&c)[4], const uint32_t (&a)[4],
                                         const uint32_t (&b)[2]) {
    asm volatile(
        "mma.sync.aligned.m16n8k16.row.col.f32.f16.f16.f32 "
        "{%0,%1,%2,%3}, {%4,%5,%6,%7}, {%8,%9}, {%0,%1,%2,%3};"
        : "+f"(c[0]), "+f"(c[1]), "+f"(c[2]), "+f"(c[3])
        : "r"(a[0]), "r"(a[1]), "r"(a[2]), "r"(a[3]), "r"(b[0]), "r"(b[1]));
}

// ---------------------------------------------------------------------------
// fp16 2-pass GEMM core:  acc = Ah @ (Bh + Bl)^T  over K=2048
//   A: fp16(x) [m][k];  B: fp16(64*W^T) hi + lo residual [n][k];  C scaled 1/64.
// CTA tile 128x128, 256 threads (8 warps: 4M x 2N, warp tile 32x64), BK=32,
// 3-stage cp.async pipeline, 2 CTAs/SM. SMEM rows padded to 80B.
// mma order: ni-pairs -> same-acc revisit distance 4 (no RAW stall).
// ---------------------------------------------------------------------------
#define BKC 32
#define KT_ (KTOT / BKC)           // 64 iterations
#define PITCH 80                   // bytes per 32-half row
#define MAT_BYTES (128 * PITCH)    // 10240 per matrix
#define STAGE_BYTES (3 * MAT_BYTES)   // Ah, Bh, Bl = 30720
#define GEMM_SMEM (3 * STAGE_BYTES)   // 92160 (2 CTAs/SM: 184320 < 227KB)
#define OSCL 0.015625f             // 1/64 weight pre-scale compensation

__device__ __forceinline__ void gemm_core(
    const __half* __restrict__ Aph,
    const __half* __restrict__ Bph, const __half* __restrict__ Bpl,
    uint32_t sbase, int tid, float (&acc)[2][8][4])
{
    const int lane = tid & 31, wid = tid >> 5;
    const int wm = wid >> 1, wn = wid & 1;

    auto load_stage = [&](int t) {
        uint32_t sb = sbase + (uint32_t)(t % 3) * STAGE_BYTES;
        const int k0 = t * BKC;
#pragma unroll
        for (int i = 0; i < 2; i++) {
            int v = tid + i * 256;
            int r = v >> 2, c = v & 3;
            uint32_t so = r * PITCH + c * 16;
            size_t go = (size_t)r * KTOT + k0 + c * 8;
            CPA(sb + so,                 Aph + go);
            CPA(sb + MAT_BYTES + so,     Bph + go);
            CPA(sb + 2 * MAT_BYTES + so, Bpl + go);
        }
        CPA_COMMIT();
    };

    load_stage(0);
    load_stage(1);

    const int arow = lane & 15, achk = lane >> 4;
    const int brow = lane & 7,  bchk = (lane >> 3) & 1;

    for (int t = 0; t < KT_; t++) {
        if (t + 1 < KT_) asm volatile("cp.async.wait_group 1;" ::: "memory");
        else             asm volatile("cp.async.wait_group 0;" ::: "memory");
        __syncthreads();
        if (t + 2 < KT_) load_stage(t + 2);

        const uint32_t sb = sbase + (uint32_t)(t % 3) * STAGE_BYTES;
#pragma unroll
        for (int ks = 0; ks < 2; ks++) {
            uint32_t ah[2][4];
#pragma unroll
            for (int mi = 0; mi < 2; mi++) {
                uint32_t ra = sb + (uint32_t)(wm * 32 + mi * 16 + arow) * PITCH
                            + ks * 32 + achk * 16;
                ldmA(ah[mi], ra);
            }
#pragma unroll
            for (int nn = 0; nn < 4; nn++) {   // ni pairs
                uint32_t bh[2][2], bl[2][2];
#pragma unroll
                for (int q = 0; q < 2; q++) {
                    int ni = nn * 2 + q;
                    uint32_t rb = sb + MAT_BYTES
                                + (uint32_t)(wn * 64 + ni * 8 + brow) * PITCH
                                + ks * 32 + bchk * 16;
                    ldmB(bh[q], rb);
                    ldmB(bl[q], rb + MAT_BYTES);
                }
                // pass-major: same-acc revisit distance = 4 mmas
#pragma unroll
                for (int q = 0; q < 2; q++)
#pragma unroll
                    for (int mi = 0; mi < 2; mi++)
                        mma16816(acc[mi][nn * 2 + q], ah[mi], bh[q]);
#pragma unroll
                for (int q = 0; q < 2; q++)
#pragma unroll
                    for (int mi = 0; mi < 2; mi++)
                        mma16816(acc[mi][nn * 2 + q], ah[mi], bl[q]);
            }
        }
    }
}

// Fused 4-projection GEMM: z in {0:q, 1:k, 2:v, 3:b}. q,k -> head layout; v,b flat.
__global__ __launch_bounds__(256, 2) void tcgemm_proj(
    const __half* __restrict__ Ah,
    const __half* __restrict__ Wth, const __half* __restrict__ Wtl,
    float* __restrict__ Cq, float* __restrict__ Ck,
    float* __restrict__ Cv, float* __restrict__ Cb)
{
    extern __shared__ char smem[];
    const uint32_t sbase = s2u(smem);
    const int tid = threadIdx.x;
    const int lane = tid & 31, wid = tid >> 5;
    const int wm = wid >> 1, wn = wid & 1;
    const int bx = blockIdx.x, by = blockIdx.y, z = blockIdx.z;
    const size_t WSZ = (size_t)H_ * H_;

    float acc[2][8][4];
#pragma unroll
    for (int mi = 0; mi < 2; mi++)
#pragma unroll
        for (int ni = 0; ni < 8; ni++)
#pragma unroll
            for (int j = 0; j < 4; j++) acc[mi][ni][j] = 0.f;

    gemm_core(Ah + (size_t)(by * 128) * KTOT,
              Wth + z * WSZ + (size_t)(bx * 128) * KTOT,
              Wtl + z * WSZ + (size_t)(bx * 128) * KTOT,
              sbase, tid, acc);

    float* C = (z == 0) ? Cq : (z == 1) ? Ck : (z == 2) ? Cv : Cb;
    const bool headlay = (z < 2);
#pragma unroll
    for (int mi = 0; mi < 2; mi++) {
        int r0 = by * 128 + wm * 32 + mi * 16 + (lane >> 2);
#pragma unroll
        for (int ni = 0; ni < 8; ni++) {
            int cc = wn * 64 + ni * 8 + (lane & 3) * 2;
            float2 lo = make_float2(acc[mi][ni][0] * OSCL, acc[mi][ni][1] * OSCL);
            float2 hi = make_float2(acc[mi][ni][2] * OSCL, acc[mi][ni][3] * OSCL);
            if (!headlay) {
                float* p = C + (size_t)r0 * H_ + bx * 128 + cc;
                *(float2*)p = lo;
                *(float2*)(p + 8 * H_) = hi;
            } else {
                int b = r0 >> 12, s = r0 & (S_ - 1);
                size_t base = ((size_t)(b * NH_ + bx) * S_ + s) * D_ + cc;
                *(float2*)(C + base) = lo;
                *(float2*)(C + base + 8 * D_) = hi;
            }
        }
    }
}

// Single GEMM (output projection), flat row-major C
__global__ __launch_bounds__(256, 2) void tcgemm_out(
    const __half* __restrict__ Ah,
    const __half* __restrict__ Bh, const __half* __restrict__ Bl,
    float* __restrict__ C)
{
    extern __shared__ char smem[];
    const uint32_t sbase = s2u(smem);
    const int tid = threadIdx.x;
    const int lane = tid & 31, wid = tid >> 5;
    const int wm = wid >> 1, wn = wid & 1;
    const int bx = blockIdx.x, by = blockIdx.y;

    float acc[2][8][4];
#pragma unroll
    for (int mi = 0; mi < 2; mi++)
#pragma unroll
        for (int ni = 0; ni < 8; ni++)
#pragma unroll
            for (int j = 0; j < 4; j++) acc[mi][ni][j] = 0.f;

    gemm_core(Ah + (size_t)(by * 128) * KTOT,
              Bh + (size_t)(bx * 128) * KTOT,
              Bl + (size_t)(bx * 128) * KTOT,
              sbase, tid, acc);

#pragma unroll
    for (int mi = 0; mi < 2; mi++) {
        int r0 = by * 128 + wm * 32 + mi * 16 + (lane >> 2);
#pragma unroll
        for (int ni = 0; ni < 8; ni++) {
            int cc = wn * 64 + ni * 8 + (lane & 3) * 2;
            float* p = C + (size_t)r0 * H_ + bx * 128 + cc;
            *(float2*)p = make_float2(acc[mi][ni][0] * OSCL, acc[mi][ni][1] * OSCL);
            *(float2*)(p + 8 * H_) = make_float2(acc[mi][ni][2] * OSCL, acc[mi][ni][3] * OSCL);
        }
    }
}

// ---------------------------------------------------------------------------
// fp32 -> fp16 convert (same layout)
// ---------------------------------------------------------------------------
struct alignas(8) hf4 { __half v[4]; };

__global__ __launch_bounds__(256) void convert_half(
    const float* __restrict__ in, __half* __restrict__ out)
{
    size_t v = (size_t)blockIdx.x * 256 + threadIdx.x;
    float4 x = *(const float4*)(in + v * 4);
    hf4 h;
    h.v[0] = __float2half_rn(x.x);
    h.v[1] = __float2half_rn(x.y);
    h.v[2] = __float2half_rn(x.z);
    h.v[3] = __float2half_rn(x.w);
    *(hf4*)(out + v * 4) = h;
}

// ---------------------------------------------------------------------------
// Fused weight transpose + scale(64) + fp16 split: all 5 weights via z
// ---------------------------------------------------------------------------
__global__ __launch_bounds__(256) void transpose_split5(
    const float* __restrict__ W0, const float* __restrict__ W1,
    const float* __restrict__ W2, const float* __restrict__ W3,
    const float* __restrict__ W4,
    __half* __restrict__ outh, __half* __restrict__ outl)
{
    __shared__ float t[32][33];
    const int z = blockIdx.z;
    const float* in = (z == 0) ? W0 : (z == 1) ? W1 : (z == 2) ? W2
                    : (z == 3) ? W3 : W4;
    const size_t WSZ = (size_t)H_ * H_;
    outh += z * WSZ;
    outl += z * WSZ;

    int x = blockIdx.x * 32 + threadIdx.x;
    int y = blockIdx.y * 32 + threadIdx.y;
#pragma unroll
    for (int i = 0; i < 32; i += 8)
        t[threadIdx.y + i][threadIdx.x] = in[(size_t)(y + i) * H_ + x];
    __syncthreads();
    x = blockIdx.y * 32 + threadIdx.x;
    y = blockIdx.x * 32 + threadIdx.y;
#pragma unroll
    for (int i = 0; i < 32; i += 8) {
        float val = t[threadIdx.x][threadIdx.y + i] * 64.0f;
        __half hh = __float2half_rn(val);
        outh[(size_t)(y + i) * H_ + x] = hh;
        outl[(size_t)(y + i) * H_ + x] = __float2half_rn(val - __half2float(hh));
    }
}

// ---------------------------------------------------------------------------
// u = sigmoid(braw) * vraw, written to head layout [bh][s][d]
// ---------------------------------------------------------------------------
__global__ __launch_bounds__(256) void ewise_u(
    const float* __restrict__ vr, const float* __restrict__ br,
    float* __restrict__ u)
{
    int v = blockIdx.x * 256 + threadIdx.x;
    int row = v >> 9;
    int col = (v & 511) * 4;
    float4 vv = *(const float4*)(vr + (size_t)row * H_ + col);
    float4 bb = *(const float4*)(br + (size_t)row * H_ + col);
    float4 r;
    r.x = vv.x / (1.f + expf(-bb.x));
    r.y = vv.y / (1.f + expf(-bb.y));
    r.z = vv.z / (1.f + expf(-bb.z));
    r.w = vv.w / (1.f + expf(-bb.w));
    int b = row >> 12, s = row & (S_ - 1);
    int h = col >> 7, d = col & 127;
    *(float4*)(u + ((size_t)(b * NH_ + h) * S_ + s) * D_ + d) = r;
}

// ---------------------------------------------------------------------------
// Per-chunk local work: att = tril(q k^T), o_intra = att @ u, P = u^T k
// ---------------------------------------------------------------------------
#define STP 132
#define CL_SMEM ((3 * 64 * STP + 64 * 65) * 4)

__global__ __launch_bounds__(256) void chunk_local(
    const float* __restrict__ q, const float* __restrict__ k,
    const float* __restrict__ u, float* __restrict__ o,
    float* __restrict__ P)
{
    extern __shared__ float sm[];
    float* sq  = sm;
    float* sk  = sm + 64 * STP;
    float* su  = sm + 2 * 64 * STP;
    float* att = sm + 3 * 64 * STP;   // [64][65]

    const int n = blockIdx.x, bh = blockIdx.y;
    const int tid = threadIdx.x;
    const size_t gbase = ((size_t)bh * S_ + n * 64) * D_;

    for (int v = tid; v < 64 * 32; v += 256) {
        int r = v >> 5, c4 = (v & 31) * 4;
        *(float4*)&sq[r * STP + c4] = *(const float4*)(q + gbase + r * 128 + c4);
        *(float4*)&sk[r * STP + c4] = *(const float4*)(k + gbase + r * 128 + c4);
        *(float4*)&su[r * STP + c4] = *(const float4*)(u + gbase + r * 128 + c4);
    }
    __syncthreads();

    {
        int i0 = (tid >> 4) * 4, j0 = (tid & 15) * 4;
        float a[4][4] = {};
        for (int e = 0; e < 128; e += 4) {
            float4 qv[4], kv[4];
#pragma unroll
            for (int r = 0; r < 4; r++) qv[r] = *(const float4*)&sq[(i0 + r) * STP + e];
#pragma unroll
            for (int c = 0; c < 4; c++) kv[c] = *(const float4*)&sk[(j0 + c) * STP + e];
#pragma unroll
            for (int r = 0; r < 4; r++)
#pragma unroll
                for (int c = 0; c < 4; c++)
                    a[r][c] += qv[r].x * kv[c].x + qv[r].y * kv[c].y
                             + qv[r].z * kv[c].z + qv[r].w * kv[c].w;
        }
#pragma unroll
        for (int r = 0; r < 4; r++)
#pragma unroll
            for (int c = 0; c < 4; c++)
                att[(i0 + r) * 65 + (j0 + c)] = (j0 + c <= i0 + r) ? a[r][c] : 0.f;
    }
    __syncthreads();

    {
        int i0 = (tid >> 4) * 4, d0 = (tid & 15) * 8;
        float acc[4][8] = {};
        for (int j = 0; j < 64; j++) {
            float am[4];
#pragma unroll
            for (int r = 0; r < 4; r++) am[r] = att[(i0 + r) * 65 + j];
            float4 u0 = *(const float4*)&su[j * STP + d0];
            float4 u1 = *(const float4*)&su[j * STP + d0 + 4];
            float uu[8] = {u0.x, u0.y, u0.z, u0.w, u1.x, u1.y, u1.z, u1.w};
#pragma unroll
            for (int r = 0; r < 4; r++)
#pragma unroll
                for (int c = 0; c < 8; c++)
                    acc[r][c] += am[r] * uu[c];
        }
        int b = bh >> 4, h = bh & 15;
#pragma unroll
        for (int r = 0; r < 4; r++) {
            float* p = o + (size_t)(b * S_ + n * 64 + i0 + r) * H_ + h * 128 + d0;
            *(float4*)(p)     = make_float4(acc[r][0], acc[r][1], acc[r][2], acc[r][3]);
            *(float4*)(p + 4) = make_float4(acc[r][4], acc[r][5], acc[r][6], acc[r][7]);
        }
    }

    {
        int d0 = (tid >> 4) * 8, e0 = (tid & 15) * 8;
        float acc[8][8] = {};
        for (int i = 0; i < 64; i++) {
            float4 ua = *(const float4*)&su[i * STP + d0];
            float4 ub = *(const float4*)&su[i * STP + d0 + 4];
            float4 ka = *(const float4*)&sk[i * STP + e0];
            float4 kb = *(const float4*)&sk[i * STP + e0 + 4];
            float uu[8] = {ua.x, ua.y, ua.z, ua.w, ub.x, ub.y, ub.z, ub.w};
            float kk[8] = {ka.x, ka.y, ka.z, ka.w, kb.x, kb.y, kb.z, kb.w};
#pragma unroll
            for (int r = 0; r < 8; r++)
#pragma unroll
                for (int c = 0; c < 8; c++)
                    acc[r][c] += uu[r] * kk[c];
        }
        float* Pp = P + ((size_t)bh * NC_ + n) * (D_ * D_);
#pragma unroll
        for (int r = 0; r < 8; r++) {
            float* p = Pp + (size_t)(d0 + r) * 128 + e0;
            *(float4*)(p)     = make_float4(acc[r][0], acc[r][1], acc[r][2], acc[r][3]);
            *(float4*)(p + 4) = make_float4(acc[r][4], acc[r][5], acc[r][6], acc[r][7]);
        }
    }
}

// ---------------------------------------------------------------------------
// Exclusive prefix over chunks of P per (bh); final state -> output tail
// ---------------------------------------------------------------------------
__global__ __launch_bounds__(256) void prefix_state(
    float* __restrict__ P, float* __restrict__ out_state)
{
    int bh = blockIdx.x >> 3;
    int part = blockIdx.x & 7;
    int idx = part * 2048 + threadIdx.x * 8;
    float acc[8] = {0, 0, 0, 0, 0, 0, 0, 0};
    float* base = P + (size_t)bh * NC_ * (D_ * D_) + idx;
    for (int nn = 0; nn < NC_; nn++) {
        float* p = base + (size_t)nn * (D_ * D_);
        float4 p0 = *(float4*)(p);
        float4 p1 = *(float4*)(p + 4);
        *(float4*)(p)     = make_float4(acc[0], acc[1], acc[2], acc[3]);
        *(float4*)(p + 4) = make_float4(acc[4], acc[5], acc[6], acc[7]);
        acc[0] += p0.x; acc[1] += p0.y; acc[2] += p0.z; acc[3] += p0.w;
        acc[4] += p1.x; acc[5] += p1.y; acc[6] += p1.z; acc[7] += p1.w;
    }
    float* q = out_state + (size_t)bh * (D_ * D_) + idx;
    *(float4*)(q)     = make_float4(acc[0], acc[1], acc[2], acc[3]);
    *(float4*)(q + 4) = make_float4(acc[4], acc[5], acc[6], acc[7]);
}

// ---------------------------------------------------------------------------
// Inter-chunk: o[i][d] += sum_e q[i][e] * S_n[d][e]
// ---------------------------------------------------------------------------
#define IN_SMEM ((64 * STP + 128 * STP) * 4)

__global__ __launch_bounds__(256) void inter_chunk(
    const float* __restrict__ q, const float* __restrict__ P,
    float* __restrict__ o)
{
    extern __shared__ float sm[];
    float* sq = sm;
    float* sS = sm + 64 * STP;

    const int n = blockIdx.x, bh = blockIdx.y;
    const int tid = threadIdx.x;
    const size_t qbase = ((size_t)bh * S_ + n * 64) * D_;
    const float* Sp = P + ((size_t)bh * NC_ + n) * (D_ * D_);

    for (int v = tid; v < 64 * 32; v += 256) {
        int r = v >> 5, c4 = (v & 31) * 4;
        *(float4*)&sq[r * STP + c4] = *(const float4*)(q + qbase + r * 128 + c4);
    }
    for (int v = tid; v < 128 * 32; v += 256) {
        int r = v >> 5, c4 = (v & 31) * 4;
        *(float4*)&sS[r * STP + c4] = *(const float4*)(Sp + (size_t)r * 128 + c4);
    }
    __syncthreads();

    int i0 = (tid >> 4) * 4, d0 = (tid & 15) * 8;
    float acc[4][8] = {};
    for (int e = 0; e < 128; e += 4) {
        float4 qv[4];
#pragma unroll
        for (int r = 0; r < 4; r++) qv[r] = *(const float4*)&sq[(i0 + r) * STP + e];
#pragma unroll
        for (int c = 0; c < 8; c++) {
            float4 sv = *(const float4*)&sS[(d0 + c) * STP + e];
#pragma unroll
            for (int r = 0; r < 4; r++)
                acc[r][c] += qv[r].x * sv.x + qv[r].y * sv.y
                           + qv[r].z * sv.z + qv[r].w * sv.w;
        }
    }
    int b = bh >> 4, h = bh & 15;
#pragma unroll
    for (int r = 0; r < 4; r++) {
        float* p = o + (size_t)(b * S_ + n * 64 + i0 + r) * H_ + h * 128 + d0;
        float4 c0 = *(float4*)(p);
        float4 c1 = *(float4*)(p + 4);
        c0.x += acc[r][0]; c0.y += acc[r][1]; c0.z += acc[r][2]; c0.w += acc[r][3];
        c1.x += acc[r][4]; c1.y += acc[r][5]; c1.z += acc[r][6]; c1.w += acc[r][7];
        *(float4*)(p)     = c0;
        *(float4*)(p + 4) = c1;
    }
}

// ---------------------------------------------------------------------------
// Launch
// ---------------------------------------------------------------------------
extern "C" void kernel_launch(void* const* d_in, const int* in_sizes, int n_in,
                              void* d_out, int out_size)
{
    (void)in_sizes; (void)n_in; (void)out_size;
    const float* x  = (const float*)d_in[0];
    const float* Wq = (const float*)d_in[1];
    const float* Wk = (const float*)d_in[2];
    const float* Wv = (const float*)d_in[3];
    const float* Wb = (const float*)d_in[4];
    const float* Wo = (const float*)d_in[5];
    float* out = (float*)d_out;
    float* out_state = out + (size_t)M_ * H_;

    float *pq, *pk, *pu, *pvr, *pbr, *po, *pP;
    __half *pxh, *poh, *pWth, *pWtl;
    cudaGetSymbolAddress((void**)&pq,  g_q);
    cudaGetSymbolAddress((void**)&pk,  g_k);
    cudaGetSymbolAddress((void**)&pu,  g_u);
    cudaGetSymbolAddress((void**)&pvr, g_vraw);
    cudaGetSymbolAddress((void**)&pbr, g_braw);
    cudaGetSymbolAddress((void**)&po,  g_o);
    cudaGetSymbolAddress((void**)&pP,  g_P);
    cudaGetSymbolAddress((void**)&pxh, g_xh);
    cudaGetSymbolAddress((void**)&poh, g_oh);
    cudaGetSymbolAddress((void**)&pWth, g_Wth);
    cudaGetSymbolAddress((void**)&pWtl, g_Wtl);

    cudaFuncSetAttribute(tcgemm_proj, cudaFuncAttributeMaxDynamicSharedMemorySize, GEMM_SMEM);
    cudaFuncSetAttribute(tcgemm_out,  cudaFuncAttributeMaxDynamicSharedMemorySize, GEMM_SMEM);
    cudaFuncSetAttribute(chunk_local, cudaFuncAttributeMaxDynamicSharedMemorySize, CL_SMEM);
    cudaFuncSetAttribute(inter_chunk, cudaFuncAttributeMaxDynamicSharedMemorySize, IN_SMEM);

    const size_t WSZ = (size_t)H_ * H_;

    dim3 tg(H_ / 32, H_ / 32, 5), tb(32, 8);
    transpose_split5<<<tg, tb>>>(Wq, Wk, Wv, Wb, Wo, pWth, pWtl);

    convert_half<<<(M_ * (H_ / 4)) / 256, 256>>>(x, pxh);

    dim3 gp(H_ / 128, M_ / 128, 4);   // (16, 64, 4) fused projections
    tcgemm_proj<<<gp, 256, GEMM_SMEM>>>(pxh, pWth, pWtl, pq, pk, pvr, pbr);

    ewise_u<<<(M_ * H_ / 4) / 256, 256>>>(pvr, pbr, pu);

    dim3 gc(NC_, B_ * NH_);      // (64, 32)
    chunk_local<<<gc, 256, CL_SMEM>>>(pq, pk, pu, po, pP);
    prefix_state<<<B_ * NH_ * 8, 256>>>(pP, out_state);
    inter_chunk<<<gc, 256, IN_SMEM>>>(pq, pP, po);

    convert_half<<<(M_ * (H_ / 4)) / 256, 256>>>(po, poh);
    dim3 go(H_ / 128, M_ / 128);
    tcgemm_out<<<go, 256, GEMM_SMEM>>>(poh, pWth + 4 * WSZ, pWtl + 4 * WSZ, out);
}

// round 9
// speedup vs baseline: 1.9174x; 1.4126x over previous
#include <cuda_runtime.h>
#include <cuda_fp16.h>
#include <math.h>
#include <stdint.h>

// Problem constants
#define B_   2
#define S_   4096
#define H_   2048
#define NH_  16
#define D_   128
#define NC_  64          // S_/64
#define M_   (B_*S_)     // 8192
#define KTOT 2048

// ---------------------------------------------------------------------------
// Scratch (device globals -- allocation-free per harness rules)
// ---------------------------------------------------------------------------
__device__ float g_q[(size_t)B_*NH_*S_*D_];     // [bh][s][d]
__device__ float g_k[(size_t)B_*NH_*S_*D_];
__device__ float g_u[(size_t)B_*NH_*S_*D_];
__device__ float g_vraw[(size_t)M_*H_];         // [row][col]
__device__ float g_braw[(size_t)M_*H_];
__device__ float g_o[(size_t)M_*H_];            // attn in [b*S+s][h*D+d] layout
__device__ float g_P[(size_t)B_*NH_*NC_*D_*D_]; // per-chunk outer products -> excl prefix
__device__ __half g_xh[(size_t)M_*H_];          // fp16 activations (x)
__device__ __half g_oh[(size_t)M_*H_];          // fp16 activations (o)
__device__ __half g_Wth[5ull*H_*H_];            // transposed weights [N][K] * 64

// ---------------------------------------------------------------------------
// PTX helpers (baseline sm_80+ only; harness targets plain sm_100)
// ---------------------------------------------------------------------------
__device__ __forceinline__ uint32_t s2u(const void* p) {
    uint32_t a;
    asm("{ .reg .u64 t; cvta.to.shared.u64 t, %1; cvt.u32.u64 %0, t; }"
        : "=r"(a) : "l"(p));
    return a;
}

#define CPA(dst, src) \
    asm volatile("cp.async.cg.shared.global [%0], [%1], 16;" :: "r"(dst), "l"(src))
#define CPA_COMMIT() asm volatile("cp.async.commit_group;" ::: "memory")

__device__ __forceinline__ void ldmA(uint32_t (&a)[4], uint32_t addr) {
    asm volatile("ldmatrix.sync.aligned.m8n8.x4.shared.b16 {%0,%1,%2,%3}, [%4];"
                 : "=r"(a[0]), "=r"(a[1]), "=r"(a[2]), "=r"(a[3]) : "r"(addr));
}
__device__ __forceinline__ void ldmB(uint32_t (&b)[2], uint32_t addr) {
    asm volatile("ldmatrix.sync.aligned.m8n8.x2.shared.b16 {%0,%1}, [%2];"
                 : "=r"(b[0]), "=r"(b[1]) : "r"(addr));
}
__device__ __forceinline__ void mma16816(float (&c)[4], const uint32_t (&a)[4],
                                         const uint32_t (&b)[2]) {
    asm volatile(
        "mma.sync.aligned.m16n8k16.row.col.f32.f16.f16.f32 "
        "{%0,%1,%2,%3}, {%4,%5,%6,%7}, {%8,%9}, {%0,%1,%2,%3};"
        : "+f"(c[0]), "+f"(c[1]), "+f"(c[2]), "+f"(c[3])
        : "r"(a[0]), "r"(a[1]), "r"(a[2]), "r"(a[3]), "r"(b[0]), "r"(b[1]));
}

// ---------------------------------------------------------------------------
// fp16 single-pass GEMM core:  acc = A @ B^T  over K=2048
//   A: fp16(x) [m][k];  B: fp16(64*W^T) [n][k];  C scaled 1/64 in epilogue.
// CTA tile 128x128, 256 threads (8 warps: 4M x 2N, warp tile 32x64), BK=32,
// 3-stage cp.async pipeline, 2 CTAs/SM. SMEM rows padded to 80B.
// ---------------------------------------------------------------------------
#define BKC 32
#define KT_ (KTOT / BKC)           // 64 iterations
#define PITCH 80                   // bytes per 32-half row
#define MAT_BYTES (128 * PITCH)    // 10240 per matrix
#define STAGE_BYTES (2 * MAT_BYTES)   // A, B = 20480
#define GEMM_SMEM (3 * STAGE_BYTES)   // 61440 (2 CTAs/SM)
#define OSCL 0.015625f             // 1/64 weight pre-scale compensation

__device__ __forceinline__ void gemm_core(
    const __half* __restrict__ Aph, const __half* __restrict__ Bph,
    uint32_t sbase, int tid, float (&acc)[2][8][4])
{
    const int lane = tid & 31, wid = tid >> 5;
    const int wm = wid >> 1, wn = wid & 1;

    auto load_stage = [&](int t) {
        uint32_t sb = sbase + (uint32_t)(t % 3) * STAGE_BYTES;
        const int k0 = t * BKC;
#pragma unroll
        for (int i = 0; i < 2; i++) {
            int v = tid + i * 256;
            int r = v >> 2, c = v & 3;
            uint32_t so = r * PITCH + c * 16;
            size_t go = (size_t)r * KTOT + k0 + c * 8;
            CPA(sb + so,             Aph + go);
            CPA(sb + MAT_BYTES + so, Bph + go);
        }
        CPA_COMMIT();
    };

    load_stage(0);
    load_stage(1);

    const int arow = lane & 15, achk = lane >> 4;
    const int brow = lane & 7,  bchk = (lane >> 3) & 1;

    for (int t = 0; t < KT_; t++) {
        if (t + 1 < KT_) asm volatile("cp.async.wait_group 1;" ::: "memory");
        else             asm volatile("cp.async.wait_group 0;" ::: "memory");
        __syncthreads();
        if (t + 2 < KT_) load_stage(t + 2);

        const uint32_t sb = sbase + (uint32_t)(t % 3) * STAGE_BYTES;
#pragma unroll
        for (int ks = 0; ks < 2; ks++) {
            uint32_t ah[2][4];
#pragma unroll
            for (int mi = 0; mi < 2; mi++) {
                uint32_t ra = sb + (uint32_t)(wm * 32 + mi * 16 + arow) * PITCH
                            + ks * 32 + achk * 16;
                ldmA(ah[mi], ra);
            }
#pragma unroll
            for (int nn = 0; nn < 4; nn++) {   // ni pairs
                uint32_t bh[2][2];
#pragma unroll
                for (int q = 0; q < 2; q++) {
                    int ni = nn * 2 + q;
                    uint32_t rb = sb + MAT_BYTES
                                + (uint32_t)(wn * 64 + ni * 8 + brow) * PITCH
                                + ks * 32 + bchk * 16;
                    ldmB(bh[q], rb);
                }
#pragma unroll
                for (int q = 0; q < 2; q++)
#pragma unroll
                    for (int mi = 0; mi < 2; mi++)
                        mma16816(acc[mi][nn * 2 + q], ah[mi], bh[q]);
            }
        }
    }
}

// Fused 4-projection GEMM: z in {0:q, 1:k, 2:v, 3:b}. q,k -> head layout; v,b flat.
__global__ __launch_bounds__(256, 2) void tcgemm_proj(
    const __half* __restrict__ Ah, const __half* __restrict__ Wth,
    float* __restrict__ Cq, float* __restrict__ Ck,
    float* __restrict__ Cv, float* __restrict__ Cb)
{
    extern __shared__ char smem[];
    const uint32_t sbase = s2u(smem);
    const int tid = threadIdx.x;
    const int lane = tid & 31, wid = tid >> 5;
    const int wm = wid >> 1, wn = wid & 1;
    const int bx = blockIdx.x, by = blockIdx.y, z = blockIdx.z;
    const size_t WSZ = (size_t)H_ * H_;

    float acc[2][8][4];
#pragma unroll
    for (int mi = 0; mi < 2; mi++)
#pragma unroll
        for (int ni = 0; ni < 8; ni++)
#pragma unroll
            for (int j = 0; j < 4; j++) acc[mi][ni][j] = 0.f;

    gemm_core(Ah + (size_t)(by * 128) * KTOT,
              Wth + z * WSZ + (size_t)(bx * 128) * KTOT,
              sbase, tid, acc);

    float* C = (z == 0) ? Cq : (z == 1) ? Ck : (z == 2) ? Cv : Cb;
    const bool headlay = (z < 2);
#pragma unroll
    for (int mi = 0; mi < 2; mi++) {
        int r0 = by * 128 + wm * 32 + mi * 16 + (lane >> 2);
#pragma unroll
        for (int ni = 0; ni < 8; ni++) {
            int cc = wn * 64 + ni * 8 + (lane & 3) * 2;
            float2 lo = make_float2(acc[mi][ni][0] * OSCL, acc[mi][ni][1] * OSCL);
            float2 hi = make_float2(acc[mi][ni][2] * OSCL, acc[mi][ni][3] * OSCL);
            if (!headlay) {
                float* p = C + (size_t)r0 * H_ + bx * 128 + cc;
                *(float2*)p = lo;
                *(float2*)(p + 8 * H_) = hi;
            } else {
                int b = r0 >> 12, s = r0 & (S_ - 1);
                size_t base = ((size_t)(b * NH_ + bx) * S_ + s) * D_ + cc;
                *(float2*)(C + base) = lo;
                *(float2*)(C + base + 8 * D_) = hi;
            }
        }
    }
}

// Single GEMM (output projection), flat row-major C
__global__ __launch_bounds__(256, 2) void tcgemm_out(
    const __half* __restrict__ Ah, const __half* __restrict__ Bh,
    float* __restrict__ C)
{
    extern __shared__ char smem[];
    const uint32_t sbase = s2u(smem);
    const int tid = threadIdx.x;
    const int lane = tid & 31, wid = tid >> 5;
    const int wm = wid >> 1, wn = wid & 1;
    const int bx = blockIdx.x, by = blockIdx.y;

    float acc[2][8][4];
#pragma unroll
    for (int mi = 0; mi < 2; mi++)
#pragma unroll
        for (int ni = 0; ni < 8; ni++)
#pragma unroll
            for (int j = 0; j < 4; j++) acc[mi][ni][j] = 0.f;

    gemm_core(Ah + (size_t)(by * 128) * KTOT,
              Bh + (size_t)(bx * 128) * KTOT,
              sbase, tid, acc);

#pragma unroll
    for (int mi = 0; mi < 2; mi++) {
        int r0 = by * 128 + wm * 32 + mi * 16 + (lane >> 2);
#pragma unroll
        for (int ni = 0; ni < 8; ni++) {
            int cc = wn * 64 + ni * 8 + (lane & 3) * 2;
            float* p = C + (size_t)r0 * H_ + bx * 128 + cc;
            *(float2*)p = make_float2(acc[mi][ni][0] * OSCL, acc[mi][ni][1] * OSCL);
            *(float2*)(p + 8 * H_) = make_float2(acc[mi][ni][2] * OSCL, acc[mi][ni][3] * OSCL);
        }
    }
}

// ---------------------------------------------------------------------------
// fp32 -> fp16 convert (same layout)
// ---------------------------------------------------------------------------
struct alignas(8) hf4 { __half v[4]; };

__global__ __launch_bounds__(256) void convert_half(
    const float* __restrict__ in, __half* __restrict__ out)
{
    size_t v = (size_t)blockIdx.x * 256 + threadIdx.x;
    float4 x = *(const float4*)(in + v * 4);
    hf4 h;
    h.v[0] = __float2half_rn(x.x);
    h.v[1] = __float2half_rn(x.y);
    h.v[2] = __float2half_rn(x.z);
    h.v[3] = __float2half_rn(x.w);
    *(hf4*)(out + v * 4) = h;
}

// ---------------------------------------------------------------------------
// Fused weight transpose + scale(64) + fp16 convert: all 5 weights via z
// ---------------------------------------------------------------------------
__global__ __launch_bounds__(256) void transpose5(
    const float* __restrict__ W0, const float* __restrict__ W1,
    const float* __restrict__ W2, const float* __restrict__ W3,
    const float* __restrict__ W4, __half* __restrict__ outh)
{
    __shared__ float t[32][33];
    const int z = blockIdx.z;
    const float* in = (z == 0) ? W0 : (z == 1) ? W1 : (z == 2) ? W2
                    : (z == 3) ? W3 : W4;
    const size_t WSZ = (size_t)H_ * H_;
    outh += z * WSZ;

    int x = blockIdx.x * 32 + threadIdx.x;
    int y = blockIdx.y * 32 + threadIdx.y;
#pragma unroll
    for (int i = 0; i < 32; i += 8)
        t[threadIdx.y + i][threadIdx.x] = in[(size_t)(y + i) * H_ + x];
    __syncthreads();
    x = blockIdx.y * 32 + threadIdx.x;
    y = blockIdx.x * 32 + threadIdx.y;
#pragma unroll
    for (int i = 0; i < 32; i += 8) {
        float val = t[threadIdx.x][threadIdx.y + i] * 64.0f;
        outh[(size_t)(y + i) * H_ + x] = __float2half_rn(val);
    }
}

// ---------------------------------------------------------------------------
// u = sigmoid(braw) * vraw, written to head layout [bh][s][d]
// ---------------------------------------------------------------------------
__global__ __launch_bounds__(256) void ewise_u(
    const float* __restrict__ vr, const float* __restrict__ br,
    float* __restrict__ u)
{
    int v = blockIdx.x * 256 + threadIdx.x;
    int row = v >> 9;
    int col = (v & 511) * 4;
    float4 vv = *(const float4*)(vr + (size_t)row * H_ + col);
    float4 bb = *(const float4*)(br + (size_t)row * H_ + col);
    float4 r;
    r.x = vv.x / (1.f + expf(-bb.x));
    r.y = vv.y / (1.f + expf(-bb.y));
    r.z = vv.z / (1.f + expf(-bb.z));
    r.w = vv.w / (1.f + expf(-bb.w));
    int b = row >> 12, s = row & (S_ - 1);
    int h = col >> 7, d = col & 127;
    *(float4*)(u + ((size_t)(b * NH_ + h) * S_ + s) * D_ + d) = r;
}

// ---------------------------------------------------------------------------
// Per-chunk local work: att = tril(q k^T), o_intra = att @ u, P = u^T k
// ---------------------------------------------------------------------------
#define STP 132
#define CL_SMEM ((3 * 64 * STP + 64 * 65) * 4)

__global__ __launch_bounds__(256) void chunk_local(
    const float* __restrict__ q, const float* __restrict__ k,
    const float* __restrict__ u, float* __restrict__ o,
    float* __restrict__ P)
{
    extern __shared__ float sm[];
    float* sq  = sm;
    float* sk  = sm + 64 * STP;
    float* su  = sm + 2 * 64 * STP;
    float* att = sm + 3 * 64 * STP;   // [64][65]

    const int n = blockIdx.x, bh = blockIdx.y;
    const int tid = threadIdx.x;
    const size_t gbase = ((size_t)bh * S_ + n * 64) * D_;

    for (int v = tid; v < 64 * 32; v += 256) {
        int r = v >> 5, c4 = (v & 31) * 4;
        *(float4*)&sq[r * STP + c4] = *(const float4*)(q + gbase + r * 128 + c4);
        *(float4*)&sk[r * STP + c4] = *(const float4*)(k + gbase + r * 128 + c4);
        *(float4*)&su[r * STP + c4] = *(const float4*)(u + gbase + r * 128 + c4);
    }
    __syncthreads();

    {
        int i0 = (tid >> 4) * 4, j0 = (tid & 15) * 4;
        float a[4][4] = {};
        for (int e = 0; e < 128; e += 4) {
            float4 qv[4], kv[4];
#pragma unroll
            for (int r = 0; r < 4; r++) qv[r] = *(const float4*)&sq[(i0 + r) * STP + e];
#pragma unroll
            for (int c = 0; c < 4; c++) kv[c] = *(const float4*)&sk[(j0 + c) * STP + e];
#pragma unroll
            for (int r = 0; r < 4; r++)
#pragma unroll
                for (int c = 0; c < 4; c++)
                    a[r][c] += qv[r].x * kv[c].x + qv[r].y * kv[c].y
                             + qv[r].z * kv[c].z + qv[r].w * kv[c].w;
        }
#pragma unroll
        for (int r = 0; r < 4; r++)
#pragma unroll
            for (int c = 0; c < 4; c++)
                att[(i0 + r) * 65 + (j0 + c)] = (j0 + c <= i0 + r) ? a[r][c] : 0.f;
    }
    __syncthreads();

    {
        int i0 = (tid >> 4) * 4, d0 = (tid & 15) * 8;
        float acc[4][8] = {};
        for (int j = 0; j < 64; j++) {
            float am[4];
#pragma unroll
            for (int r = 0; r < 4; r++) am[r] = att[(i0 + r) * 65 + j];
            float4 u0 = *(const float4*)&su[j * STP + d0];
            float4 u1 = *(const float4*)&su[j * STP + d0 + 4];
            float uu[8] = {u0.x, u0.y, u0.z, u0.w, u1.x, u1.y, u1.z, u1.w};
#pragma unroll
            for (int r = 0; r < 4; r++)
#pragma unroll
                for (int c = 0; c < 8; c++)
                    acc[r][c] += am[r] * uu[c];
        }
        int b = bh >> 4, h = bh & 15;
#pragma unroll
        for (int r = 0; r < 4; r++) {
            float* p = o + (size_t)(b * S_ + n * 64 + i0 + r) * H_ + h * 128 + d0;
            *(float4*)(p)     = make_float4(acc[r][0], acc[r][1], acc[r][2], acc[r][3]);
            *(float4*)(p + 4) = make_float4(acc[r][4], acc[r][5], acc[r][6], acc[r][7]);
        }
    }

    {
        int d0 = (tid >> 4) * 8, e0 = (tid & 15) * 8;
        float acc[8][8] = {};
        for (int i = 0; i < 64; i++) {
            float4 ua = *(const float4*)&su[i * STP + d0];
            float4 ub = *(const float4*)&su[i * STP + d0 + 4];
            float4 ka = *(const float4*)&sk[i * STP + e0];
            float4 kb = *(const float4*)&sk[i * STP + e0 + 4];
            float uu[8] = {ua.x, ua.y, ua.z, ua.w, ub.x, ub.y, ub.z, ub.w};
            float kk[8] = {ka.x, ka.y, ka.z, ka.w, kb.x, kb.y, kb.z, kb.w};
#pragma unroll
            for (int r = 0; r < 8; r++)
#pragma unroll
                for (int c = 0; c < 8; c++)
                    acc[r][c] += uu[r] * kk[c];
        }
        float* Pp = P + ((size_t)bh * NC_ + n) * (D_ * D_);
#pragma unroll
        for (int r = 0; r < 8; r++) {
            float* p = Pp + (size_t)(d0 + r) * 128 + e0;
            *(float4*)(p)     = make_float4(acc[r][0], acc[r][1], acc[r][2], acc[r][3]);
            *(float4*)(p + 4) = make_float4(acc[r][4], acc[r][5], acc[r][6], acc[r][7]);
        }
    }
}

// ---------------------------------------------------------------------------
// Exclusive prefix over chunks of P per (bh); final state -> output tail
// ---------------------------------------------------------------------------
__global__ __launch_bounds__(256) void prefix_state(
    float* __restrict__ P, float* __restrict__ out_state)
{
    int bh = blockIdx.x >> 3;
    int part = blockIdx.x & 7;
    int idx = part * 2048 + threadIdx.x * 8;
    float acc[8] = {0, 0, 0, 0, 0, 0, 0, 0};
    float* base = P + (size_t)bh * NC_ * (D_ * D_) + idx;
    for (int nn = 0; nn < NC_; nn++) {
        float* p = base + (size_t)nn * (D_ * D_);
        float4 p0 = *(float4*)(p);
        float4 p1 = *(float4*)(p + 4);
        *(float4*)(p)     = make_float4(acc[0], acc[1], acc[2], acc[3]);
        *(float4*)(p + 4) = make_float4(acc[4], acc[5], acc[6], acc[7]);
        acc[0] += p0.x; acc[1] += p0.y; acc[2] += p0.z; acc[3] += p0.w;
        acc[4] += p1.x; acc[5] += p1.y; acc[6] += p1.z; acc[7] += p1.w;
    }
    float* q = out_state + (size_t)bh * (D_ * D_) + idx;
    *(float4*)(q)     = make_float4(acc[0], acc[1], acc[2], acc[3]);
    *(float4*)(q + 4) = make_float4(acc[4], acc[5], acc[6], acc[7]);
}

// ---------------------------------------------------------------------------
// Inter-chunk: o[i][d] += sum_e q[i][e] * S_n[d][e]
// ---------------------------------------------------------------------------
#define IN_SMEM ((64 * STP + 128 * STP) * 4)

__global__ __launch_bounds__(256) void inter_chunk(
    const float* __restrict__ q, const float* __restrict__ P,
    float* __restrict__ o)
{
    extern __shared__ float sm[];
    float* sq = sm;
    float* sS = sm + 64 * STP;

    const int n = blockIdx.x, bh = blockIdx.y;
    const int tid = threadIdx.x;
    const size_t qbase = ((size_t)bh * S_ + n * 64) * D_;
    const float* Sp = P + ((size_t)bh * NC_ + n) * (D_ * D_);

    for (int v = tid; v < 64 * 32; v += 256) {
        int r = v >> 5, c4 = (v & 31) * 4;
        *(float4*)&sq[r * STP + c4] = *(const float4*)(q + qbase + r * 128 + c4);
    }
    for (int v = tid; v < 128 * 32; v += 256) {
        int r = v >> 5, c4 = (v & 31) * 4;
        *(float4*)&sS[r * STP + c4] = *(const float4*)(Sp + (size_t)r * 128 + c4);
    }
    __syncthreads();

    int i0 = (tid >> 4) * 4, d0 = (tid & 15) * 8;
    float acc[4][8] = {};
    for (int e = 0; e < 128; e += 4) {
        float4 qv[4];
#pragma unroll
        for (int r = 0; r < 4; r++) qv[r] = *(const float4*)&sq[(i0 + r) * STP + e];
#pragma unroll
        for (int c = 0; c < 8; c++) {
            float4 sv = *(const float4*)&sS[(d0 + c) * STP + e];
#pragma unroll
            for (int r = 0; r < 4; r++)
                acc[r][c] += qv[r].x * sv.x + qv[r].y * sv.y
                           + qv[r].z * sv.z + qv[r].w * sv.w;
        }
    }
    int b = bh >> 4, h = bh & 15;
#pragma unroll
    for (int r = 0; r < 4; r++) {
        float* p = o + (size_t)(b * S_ + n * 64 + i0 + r) * H_ + h * 128 + d0;
        float4 c0 = *(float4*)(p);
        float4 c1 = *(float4*)(p + 4);
        c0.x += acc[r][0]; c0.y += acc[r][1]; c0.z += acc[r][2]; c0.w += acc[r][3];
        c1.x += acc[r][4]; c1.y += acc[r][5]; c1.z += acc[r][6]; c1.w += acc[r][7];
        *(float4*)(p)     = c0;
        *(float4*)(p + 4) = c1;
    }
}

// ---------------------------------------------------------------------------
// Launch
// ---------------------------------------------------------------------------
extern "C" void kernel_launch(void* const* d_in, const int* in_sizes, int n_in,
                              void* d_out, int out_size)
{
    (void)in_sizes; (void)n_in; (void)out_size;
    const float* x  = (const float*)d_in[0];
    const float* Wq = (const float*)d_in[1];
    const float* Wk = (const float*)d_in[2];
    const float* Wv = (const float*)d_in[3];
    const float* Wb = (const float*)d_in[4];
    const float* Wo = (const float*)d_in[5];
    float* out = (float*)d_out;
    float* out_state = out + (size_t)M_ * H_;

    float *pq, *pk, *pu, *pvr, *pbr, *po, *pP;
    __half *pxh, *poh, *pWth;
    cudaGetSymbolAddress((void**)&pq,  g_q);
    cudaGetSymbolAddress((void**)&pk,  g_k);
    cudaGetSymbolAddress((void**)&pu,  g_u);
    cudaGetSymbolAddress((void**)&pvr, g_vraw);
    cudaGetSymbolAddress((void**)&pbr, g_braw);
    cudaGetSymbolAddress((void**)&po,  g_o);
    cudaGetSymbolAddress((void**)&pP,  g_P);
    cudaGetSymbolAddress((void**)&pxh, g_xh);
    cudaGetSymbolAddress((void**)&poh, g_oh);
    cudaGetSymbolAddress((void**)&pWth, g_Wth);

    cudaFuncSetAttribute(tcgemm_proj, cudaFuncAttributeMaxDynamicSharedMemorySize, GEMM_SMEM);
    cudaFuncSetAttribute(tcgemm_out,  cudaFuncAttributeMaxDynamicSharedMemorySize, GEMM_SMEM);
    cudaFuncSetAttribute(chunk_local, cudaFuncAttributeMaxDynamicSharedMemorySize, CL_SMEM);
    cudaFuncSetAttribute(inter_chunk, cudaFuncAttributeMaxDynamicSharedMemorySize, IN_SMEM);

    const size_t WSZ = (size_t)H_ * H_;

    dim3 tg(H_ / 32, H_ / 32, 5), tb(32, 8);
    transpose5<<<tg, tb>>>(Wq, Wk, Wv, Wb, Wo, pWth);

    convert_half<<<(M_ * (H_ / 4)) / 256, 256>>>(x, pxh);

    dim3 gp(H_ / 128, M_ / 128, 4);   // (16, 64, 4) fused projections
    tcgemm_proj<<<gp, 256, GEMM_SMEM>>>(pxh, pWth, pq, pk, pvr, pbr);

    ewise_u<<<(M_ * H_ / 4) / 256, 256>>>(pvr, pbr, pu);

    dim3 gc(NC_, B_ * NH_);      // (64, 32)
    chunk_local<<<gc, 256, CL_SMEM>>>(pq, pk, pu, po, pP);
    prefix_state<<<B_ * NH_ * 8, 256>>>(pP, out_state);
    inter_chunk<<<gc, 256, IN_SMEM>>>(pq, pP, po);

    convert_half<<<(M_ * (H_ / 4)) / 256, 256>>>(po, poh);
    dim3 go(H_ / 128, M_ / 128);
    tcgemm_out<<<go, 256, GEMM_SMEM>>>(poh, pWth + 4 * WSZ, out);
}

// round 10
// speedup vs baseline: 3.3543x; 1.7494x over previous
#include <cuda_runtime.h>
#include <cuda_fp16.h>
#include <math.h>
#include <stdint.h>

// Problem constants
#define B_   2
#define S_   4096
#define H_   2048
#define NH_  16
#define D_   128
#define NC_  64          // S_/64
#define M_   (B_*S_)     // 8192
#define KTOT 2048

// ---------------------------------------------------------------------------
// Scratch (device globals -- allocation-free per harness rules)
// ---------------------------------------------------------------------------
__device__ __half g_qh[(size_t)B_*NH_*S_*D_];   // fp16 [bh][s][d]
__device__ __half g_kh[(size_t)B_*NH_*S_*D_];
__device__ __half g_uh[(size_t)B_*NH_*S_*D_];
__device__ __half g_vh[(size_t)M_*H_];          // fp16 flat
__device__ __half g_bb[(size_t)M_*H_];
__device__ float  g_o[(size_t)M_*H_];           // intra-chunk attn, fp32 flat
__device__ float  g_P[(size_t)B_*NH_*NC_*D_*D_];// per-chunk outer products (fp32)
__device__ __half g_Sh[(size_t)B_*NH_*NC_*D_*D_];// exclusive-prefix states (fp16)
__device__ __half g_xh[(size_t)M_*H_];          // fp16 activations (x)
__device__ __half g_oh[(size_t)M_*H_];          // fp16 attn (final, for out proj)
__device__ __half g_Wth[5ull*H_*H_];            // transposed weights [N][K] * 64

// ---------------------------------------------------------------------------
// PTX helpers (baseline sm_80+ only; harness targets plain sm_100)
// ---------------------------------------------------------------------------
__device__ __forceinline__ uint32_t s2u(const void* p) {
    uint32_t a;
    asm("{ .reg .u64 t; cvta.to.shared.u64 t, %1; cvt.u32.u64 %0, t; }"
        : "=r"(a) : "l"(p));
    return a;
}

#define CPA(dst, src) \
    asm volatile("cp.async.cg.shared.global [%0], [%1], 16;" :: "r"(dst), "l"(src))
#define CPA_COMMIT() asm volatile("cp.async.commit_group;" ::: "memory")

__device__ __forceinline__ void ldmA(uint32_t (&a)[4], uint32_t addr) {
    asm volatile("ldmatrix.sync.aligned.m8n8.x4.shared.b16 {%0,%1,%2,%3}, [%4];"
                 : "=r"(a[0]), "=r"(a[1]), "=r"(a[2]), "=r"(a[3]) : "r"(addr));
}
__device__ __forceinline__ void ldmAT(uint32_t (&a)[4], uint32_t addr) {
    asm volatile("ldmatrix.sync.aligned.m8n8.x4.trans.shared.b16 {%0,%1,%2,%3}, [%4];"
                 : "=r"(a[0]), "=r"(a[1]), "=r"(a[2]), "=r"(a[3]) : "r"(addr));
}
__device__ __forceinline__ void ldmB(uint32_t (&b)[2], uint32_t addr) {
    asm volatile("ldmatrix.sync.aligned.m8n8.x2.shared.b16 {%0,%1}, [%2];"
                 : "=r"(b[0]), "=r"(b[1]) : "r"(addr));
}
__device__ __forceinline__ void ldmBT(uint32_t (&b)[2], uint32_t addr) {
    asm volatile("ldmatrix.sync.aligned.m8n8.x2.trans.shared.b16 {%0,%1}, [%2];"
                 : "=r"(b[0]), "=r"(b[1]) : "r"(addr));
}
__device__ __forceinline__ void mma16816(float (&c)[4], const uint32_t (&a)[4],
                                         const uint32_t (&b)[2]) {
    asm volatile(
        "mma.sync.aligned.m16n8k16.row.col.f32.f16.f16.f32 "
        "{%0,%1,%2,%3}, {%4,%5,%6,%7}, {%8,%9}, {%0,%1,%2,%3};"
        : "+f"(c[0]), "+f"(c[1]), "+f"(c[2]), "+f"(c[3])
        : "r"(a[0]), "r"(a[1]), "r"(a[2]), "r"(a[3]), "r"(b[0]), "r"(b[1]));
}

// ---------------------------------------------------------------------------
// fp16 single-pass GEMM core:  acc = A @ B^T  over K=2048 (unchanged from R9)
// ---------------------------------------------------------------------------
#define BKC 32
#define KT_ (KTOT / BKC)
#define PITCH 80
#define MAT_BYTES (128 * PITCH)
#define STAGE_BYTES (2 * MAT_BYTES)
#define GEMM_SMEM (3 * STAGE_BYTES)
#define OSCL 0.015625f

__device__ __forceinline__ void gemm_core(
    const __half* __restrict__ Aph, const __half* __restrict__ Bph,
    uint32_t sbase, int tid, float (&acc)[2][8][4])
{
    const int lane = tid & 31, wid = tid >> 5;
    const int wm = wid >> 1, wn = wid & 1;

    auto load_stage = [&](int t) {
        uint32_t sb = sbase + (uint32_t)(t % 3) * STAGE_BYTES;
        const int k0 = t * BKC;
#pragma unroll
        for (int i = 0; i < 2; i++) {
            int v = tid + i * 256;
            int r = v >> 2, c = v & 3;
            uint32_t so = r * PITCH + c * 16;
            size_t go = (size_t)r * KTOT + k0 + c * 8;
            CPA(sb + so,             Aph + go);
            CPA(sb + MAT_BYTES + so, Bph + go);
        }
        CPA_COMMIT();
    };

    load_stage(0);
    load_stage(1);

    const int arow = lane & 15, achk = lane >> 4;
    const int brow = lane & 7,  bchk = (lane >> 3) & 1;

    for (int t = 0; t < KT_; t++) {
        if (t + 1 < KT_) asm volatile("cp.async.wait_group 1;" ::: "memory");
        else             asm volatile("cp.async.wait_group 0;" ::: "memory");
        __syncthreads();
        if (t + 2 < KT_) load_stage(t + 2);

        const uint32_t sb = sbase + (uint32_t)(t % 3) * STAGE_BYTES;
#pragma unroll
        for (int ks = 0; ks < 2; ks++) {
            uint32_t ah[2][4];
#pragma unroll
            for (int mi = 0; mi < 2; mi++) {
                uint32_t ra = sb + (uint32_t)(wm * 32 + mi * 16 + arow) * PITCH
                            + ks * 32 + achk * 16;
                ldmA(ah[mi], ra);
            }
#pragma unroll
            for (int nn = 0; nn < 4; nn++) {
                uint32_t bh2[2][2];
#pragma unroll
                for (int q = 0; q < 2; q++) {
                    int ni = nn * 2 + q;
                    uint32_t rb = sb + MAT_BYTES
                                + (uint32_t)(wn * 64 + ni * 8 + brow) * PITCH
                                + ks * 32 + bchk * 16;
                    ldmB(bh2[q], rb);
                }
#pragma unroll
                for (int q = 0; q < 2; q++)
#pragma unroll
                    for (int mi = 0; mi < 2; mi++)
                        mma16816(acc[mi][nn * 2 + q], ah[mi], bh2[q]);
            }
        }
    }
}

// Fused 4-projection GEMM: z in {0:q, 1:k, 2:v, 3:b}. Outputs fp16.
__global__ __launch_bounds__(256, 2) void tcgemm_proj(
    const __half* __restrict__ Ah, const __half* __restrict__ Wth,
    __half* __restrict__ Cq, __half* __restrict__ Ck,
    __half* __restrict__ Cv, __half* __restrict__ Cb)
{
    extern __shared__ char smem[];
    const uint32_t sbase = s2u(smem);
    const int tid = threadIdx.x;
    const int lane = tid & 31, wid = tid >> 5;
    const int wm = wid >> 1, wn = wid & 1;
    const int bx = blockIdx.x, by = blockIdx.y, z = blockIdx.z;
    const size_t WSZ = (size_t)H_ * H_;

    float acc[2][8][4];
#pragma unroll
    for (int mi = 0; mi < 2; mi++)
#pragma unroll
        for (int ni = 0; ni < 8; ni++)
#pragma unroll
            for (int j = 0; j < 4; j++) acc[mi][ni][j] = 0.f;

    gemm_core(Ah + (size_t)(by * 128) * KTOT,
              Wth + z * WSZ + (size_t)(bx * 128) * KTOT,
              sbase, tid, acc);

    __half* C = (z == 0) ? Cq : (z == 1) ? Ck : (z == 2) ? Cv : Cb;
    const bool headlay = (z < 2);
#pragma unroll
    for (int mi = 0; mi < 2; mi++) {
        int r0 = by * 128 + wm * 32 + mi * 16 + (lane >> 2);
#pragma unroll
        for (int ni = 0; ni < 8; ni++) {
            int cc = wn * 64 + ni * 8 + (lane & 3) * 2;
            __half2 lo = __floats2half2_rn(acc[mi][ni][0] * OSCL, acc[mi][ni][1] * OSCL);
            __half2 hi = __floats2half2_rn(acc[mi][ni][2] * OSCL, acc[mi][ni][3] * OSCL);
            if (!headlay) {
                __half* p = C + (size_t)r0 * H_ + bx * 128 + cc;
                *(__half2*)p = lo;
                *(__half2*)(p + 8 * H_) = hi;
            } else {
                int b = r0 >> 12, s = r0 & (S_ - 1);
                size_t base = ((size_t)(b * NH_ + bx) * S_ + s) * D_ + cc;
                *(__half2*)(C + base) = lo;
                *(__half2*)(C + base + 8 * D_) = hi;
            }
        }
    }
}

// Output projection GEMM: fp32 result
__global__ __launch_bounds__(256, 2) void tcgemm_out(
    const __half* __restrict__ Ah, const __half* __restrict__ Bh,
    float* __restrict__ C)
{
    extern __shared__ char smem[];
    const uint32_t sbase = s2u(smem);
    const int tid = threadIdx.x;
    const int lane = tid & 31, wid = tid >> 5;
    const int wm = wid >> 1, wn = wid & 1;
    const int bx = blockIdx.x, by = blockIdx.y;

    float acc[2][8][4];
#pragma unroll
    for (int mi = 0; mi < 2; mi++)
#pragma unroll
        for (int ni = 0; ni < 8; ni++)
#pragma unroll
            for (int j = 0; j < 4; j++) acc[mi][ni][j] = 0.f;

    gemm_core(Ah + (size_t)(by * 128) * KTOT,
              Bh + (size_t)(bx * 128) * KTOT, sbase, tid, acc);

#pragma unroll
    for (int mi = 0; mi < 2; mi++) {
        int r0 = by * 128 + wm * 32 + mi * 16 + (lane >> 2);
#pragma unroll
        for (int ni = 0; ni < 8; ni++) {
            int cc = wn * 64 + ni * 8 + (lane & 3) * 2;
            float* p = C + (size_t)r0 * H_ + bx * 128 + cc;
            *(float2*)p = make_float2(acc[mi][ni][0] * OSCL, acc[mi][ni][1] * OSCL);
            *(float2*)(p + 8 * H_) = make_float2(acc[mi][ni][2] * OSCL, acc[mi][ni][3] * OSCL);
        }
    }
}

// ---------------------------------------------------------------------------
// fp32 -> fp16 convert (x only)
// ---------------------------------------------------------------------------
struct alignas(8) hf4 { __half v[4]; };

__global__ __launch_bounds__(256) void convert_half(
    const float* __restrict__ in, __half* __restrict__ out)
{
    size_t v = (size_t)blockIdx.x * 256 + threadIdx.x;
    float4 x = *(const float4*)(in + v * 4);
    hf4 h;
    h.v[0] = __float2half_rn(x.x);
    h.v[1] = __float2half_rn(x.y);
    h.v[2] = __float2half_rn(x.z);
    h.v[3] = __float2half_rn(x.w);
    *(hf4*)(out + v * 4) = h;
}

// ---------------------------------------------------------------------------
// Fused weight transpose + scale(64) + fp16 convert: all 5 weights via z
// ---------------------------------------------------------------------------
__global__ __launch_bounds__(256) void transpose5(
    const float* __restrict__ W0, const float* __restrict__ W1,
    const float* __restrict__ W2, const float* __restrict__ W3,
    const float* __restrict__ W4, __half* __restrict__ outh)
{
    __shared__ float t[32][33];
    const int z = blockIdx.z;
    const float* in = (z == 0) ? W0 : (z == 1) ? W1 : (z == 2) ? W2
                    : (z == 3) ? W3 : W4;
    const size_t WSZ = (size_t)H_ * H_;
    outh += z * WSZ;

    int x = blockIdx.x * 32 + threadIdx.x;
    int y = blockIdx.y * 32 + threadIdx.y;
#pragma unroll
    for (int i = 0; i < 32; i += 8)
        t[threadIdx.y + i][threadIdx.x] = in[(size_t)(y + i) * H_ + x];
    __syncthreads();
    x = blockIdx.y * 32 + threadIdx.x;
    y = blockIdx.x * 32 + threadIdx.y;
#pragma unroll
    for (int i = 0; i < 32; i += 8)
        outh[(size_t)(y + i) * H_ + x] =
            __float2half_rn(t[threadIdx.x][threadIdx.y + i] * 64.0f);
}

// ---------------------------------------------------------------------------
// u = sigmoid(b) * v  (fp16 in flat, fp16 out head layout)
// ---------------------------------------------------------------------------
__global__ __launch_bounds__(256) void ewise_u(
    const __half* __restrict__ vr, const __half* __restrict__ br,
    __half* __restrict__ u)
{
    int v = blockIdx.x * 256 + threadIdx.x;    // 8-half chunk index
    int row = v >> 8;                          // 256 chunks per row
    int col = (v & 255) * 8;
    float4 vv4 = *(const float4*)(vr + (size_t)row * H_ + col);
    float4 bb4 = *(const float4*)(br + (size_t)row * H_ + col);
    const __half2* vp = (const __half2*)&vv4;
    const __half2* bp = (const __half2*)&bb4;
    float4 out4;
    __half2* op = (__half2*)&out4;
#pragma unroll
    for (int i = 0; i < 4; i++) {
        float2 vf = __half22float2(vp[i]);
        float2 bf = __half22float2(bp[i]);
        op[i] = __floats2half2_rn(vf.x / (1.f + expf(-bf.x)),
                                  vf.y / (1.f + expf(-bf.y)));
    }
    int b = row >> 12, s = row & (S_ - 1);
    int h = col >> 7, d = col & 127;
    *(float4*)(u + ((size_t)(b * NH_ + h) * S_ + s) * D_ + d) = out4;
}

// ---------------------------------------------------------------------------
// Tensorized per-chunk local work (fp16 mma):
//   att = tril(q k^T); o_intra = att @ u; P = u^T k
// 256 threads, 8 warps (4M x 2N). q,k,u tiles [64][128] fp16 in smem.
// ---------------------------------------------------------------------------
#define PH 272    // bytes per 128-half row (r*272 mod 128 = r*16 -> conflict free)
#define PA 144    // bytes per 64-half att row
#define CL_SMEM (3 * 64 * PH + 64 * PA)   // 61440

__global__ __launch_bounds__(256) void chunk_local(
    const __half* __restrict__ q, const __half* __restrict__ k,
    const __half* __restrict__ u, float* __restrict__ o,
    float* __restrict__ P)
{
    extern __shared__ char smc[];
    const uint32_t sq = s2u(smc);
    const uint32_t sk = sq + 64 * PH;
    const uint32_t su = sk + 64 * PH;
    const uint32_t sa = su + 64 * PH;

    const int n = blockIdx.x, bh = blockIdx.y;
    const int tid = threadIdx.x;
    const int lane = tid & 31, wid = tid >> 5;
    const int wm = wid >> 1, wn = wid & 1;     // 4M x 2N
    const size_t gbase = ((size_t)bh * S_ + n * 64) * D_;

    // load q,k,u tiles (64 x 128 half, 16 chunks of 16B per row)
#pragma unroll
    for (int i = 0; i < 4; i++) {
        int v = tid + i * 256;
        int r = v >> 4, c = v & 15;
        size_t go = gbase + r * 128 + c * 8;
        uint32_t so = r * PH + c * 16;
        *(float4*)(smc + (sq - s2u(smc)) + so) = *(const float4*)(q + go);
        *(float4*)(smc + (sk - s2u(smc)) + so) = *(const float4*)(k + go);
        *(float4*)(smc + (su - s2u(smc)) + so) = *(const float4*)(u + go);
    }
    __syncthreads();

    const int r = lane >> 2, cb = (lane & 3) * 2;
    const int b = bh >> 4, h = bh & 15;

    // ---- att = tril(q k^T): warp tile 16(m=i) x 32(n=j) ----
    {
        float a[4][4] = {};
#pragma unroll
        for (int ks = 0; ks < 8; ks++) {          // k = e over 128
            uint32_t af[4];
            ldmA(af, sq + (uint32_t)(wm * 16 + (lane & 15)) * PH
                       + ks * 32 + (lane >> 4) * 16);
#pragma unroll
            for (int nf = 0; nf < 4; nf++) {
                uint32_t bf[2];
                ldmB(bf, sk + (uint32_t)(wn * 32 + nf * 8 + (lane & 7)) * PH
                           + ks * 32 + ((lane >> 3) & 1) * 16);
                mma16816(a[nf], af, bf);
            }
        }
        // mask (j <= i) + store fp16 to att smem
#pragma unroll
        for (int nf = 0; nf < 4; nf++) {
            int row0 = wm * 16 + r, row1 = row0 + 8;
            int col = wn * 32 + nf * 8 + cb;
            float c0 = (col     <= row0) ? a[nf][0] : 0.f;
            float c1 = (col + 1 <= row0) ? a[nf][1] : 0.f;
            float c2 = (col     <= row1) ? a[nf][2] : 0.f;
            float c3 = (col + 1 <= row1) ? a[nf][3] : 0.f;
            *(__half2*)(smc + (sa - s2u(smc)) + row0 * PA + col * 2) = __floats2half2_rn(c0, c1);
            *(__half2*)(smc + (sa - s2u(smc)) + row1 * PA + col * 2) = __floats2half2_rn(c2, c3);
        }
    }
    __syncthreads();

    // ---- o_intra = att @ u: warp tile 16(m=i) x 64(n=d) ----
    {
        float oacc[8][4] = {};
#pragma unroll
        for (int ks = 0; ks < 4; ks++) {          // k = j over 64
            uint32_t af[4];
            ldmA(af, sa + (uint32_t)(wm * 16 + (lane & 15)) * PA
                       + ks * 32 + (lane >> 4) * 16);
#pragma unroll
            for (int nf = 0; nf < 8; nf++) {
                int dbase = wn * 64 + nf * 8;
                uint32_t bf[2];
                // B[n=d][k=j] from u[j][d] via x2.trans: lanes 0-15 -> rows j
                ldmBT(bf, su + (uint32_t)(ks * 16 + (lane & 15)) * PH + dbase * 2);
                mma16816(oacc[nf], af, bf);
            }
        }
#pragma unroll
        for (int nf = 0; nf < 8; nf++) {
            int d = wn * 64 + nf * 8 + cb;
            int i0 = wm * 16 + r;
            float* p0 = o + ((size_t)(b * S_ + n * 64 + i0)) * H_ + h * 128 + d;
            *(float2*)p0 = make_float2(oacc[nf][0], oacc[nf][1]);
            *(float2*)(p0 + 8 * H_) = make_float2(oacc[nf][2], oacc[nf][3]);
        }
    }

    // ---- P = u^T k: warp tile 32(m=d) x 64(n=e) ----
    {
        float pc[2][8][4] = {};
#pragma unroll
        for (int ks = 0; ks < 4; ks++) {          // k = j over 64
            uint32_t af[2][4];
#pragma unroll
            for (int mf = 0; mf < 2; mf++) {
                int dm = wm * 32 + mf * 16;
                // A[m=d][k=j] from u[j][d] via x4.trans
                int rowj = ks * 16 + ((lane >> 4) & 1) * 8 + (lane & 7);
                int dcol = dm + ((lane >> 3) & 1) * 8;
                ldmAT(af[mf], su + (uint32_t)rowj * PH + dcol * 2);
            }
#pragma unroll
            for (int nf = 0; nf < 8; nf++) {
                int ebase = wn * 64 + nf * 8;
                uint32_t bf[2];
                ldmBT(bf, sk + (uint32_t)(ks * 16 + (lane & 15)) * PH + ebase * 2);
#pragma unroll
                for (int mf = 0; mf < 2; mf++)
                    mma16816(pc[mf][nf], af[mf], bf);
            }
        }
        float* Pp = P + ((size_t)bh * NC_ + n) * (D_ * D_);
#pragma unroll
        for (int mf = 0; mf < 2; mf++)
#pragma unroll
            for (int nf = 0; nf < 8; nf++) {
                int d = wm * 32 + mf * 16 + r;
                int e = wn * 64 + nf * 8 + cb;
                float* pp = Pp + (size_t)d * 128 + e;
                *(float2*)pp = make_float2(pc[mf][nf][0], pc[mf][nf][1]);
                *(float2*)(pp + 8 * 128) = make_float2(pc[mf][nf][2], pc[mf][nf][3]);
            }
    }
}

// ---------------------------------------------------------------------------
// Exclusive prefix over chunks of P per (bh) -> S (fp16); final state -> out
// ---------------------------------------------------------------------------
__global__ __launch_bounds__(256) void prefix_state(
    const float* __restrict__ P, __half* __restrict__ Sh,
    float* __restrict__ out_state)
{
    int bh = blockIdx.x >> 3;
    int part = blockIdx.x & 7;
    int idx = part * 2048 + threadIdx.x * 8;
    float acc[8] = {0, 0, 0, 0, 0, 0, 0, 0};
    const float* base = P + (size_t)bh * NC_ * (D_ * D_) + idx;
    __half* sbase = Sh + (size_t)bh * NC_ * (D_ * D_) + idx;
    for (int nn = 0; nn < NC_; nn++) {
        const float* p = base + (size_t)nn * (D_ * D_);
        float4 p0 = *(const float4*)(p);
        float4 p1 = *(const float4*)(p + 4);
        float4 hv;
        __half2* hp = (__half2*)&hv;
        hp[0] = __floats2half2_rn(acc[0], acc[1]);
        hp[1] = __floats2half2_rn(acc[2], acc[3]);
        hp[2] = __floats2half2_rn(acc[4], acc[5]);
        hp[3] = __floats2half2_rn(acc[6], acc[7]);
        *(float4*)(sbase + (size_t)nn * (D_ * D_)) = hv;
        acc[0] += p0.x; acc[1] += p0.y; acc[2] += p0.z; acc[3] += p0.w;
        acc[4] += p1.x; acc[5] += p1.y; acc[6] += p1.z; acc[7] += p1.w;
    }
    float* qo = out_state + (size_t)bh * (D_ * D_) + idx;
    *(float4*)(qo)     = make_float4(acc[0], acc[1], acc[2], acc[3]);
    *(float4*)(qo + 4) = make_float4(acc[4], acc[5], acc[6], acc[7]);
}

// ---------------------------------------------------------------------------
// Tensorized inter-chunk: oh = fp16(o_intra + q @ S^T)
// 256 threads, 8 warps (4M x 2N). q [64][128], S [128][128] fp16 in smem.
// ---------------------------------------------------------------------------
#define IN_SMEM (64 * PH + 128 * PH)   // 52224

__global__ __launch_bounds__(256) void inter_chunk(
    const __half* __restrict__ q, const __half* __restrict__ Sh,
    const float* __restrict__ o, __half* __restrict__ oh)
{
    extern __shared__ char smc[];
    const uint32_t sq = s2u(smc);
    const uint32_t sS = sq + 64 * PH;

    const int n = blockIdx.x, bh = blockIdx.y;
    const int tid = threadIdx.x;
    const int lane = tid & 31, wid = tid >> 5;
    const int wm = wid >> 1, wn = wid & 1;
    const size_t qbase = ((size_t)bh * S_ + n * 64) * D_;
    const __half* Sp = Sh + ((size_t)bh * NC_ + n) * (D_ * D_);

#pragma unroll
    for (int i = 0; i < 4; i++) {       // q: 1024 chunks
        int v = tid + i * 256;
        int rr = v >> 4, c = v & 15;
        *(float4*)(smc + rr * PH + c * 16) = *(const float4*)(q + qbase + rr * 128 + c * 8);
    }
#pragma unroll
    for (int i = 0; i < 8; i++) {       // S: 2048 chunks
        int v = tid + i * 256;
        int rr = v >> 4, c = v & 15;
        *(float4*)(smc + 64 * PH + rr * PH + c * 16) = *(const float4*)(Sp + rr * 128 + c * 8);
    }
    __syncthreads();

    float acc[8][4] = {};
#pragma unroll
    for (int ks = 0; ks < 8; ks++) {    // k = e over 128
        uint32_t af[4];
        ldmA(af, sq + (uint32_t)(wm * 16 + (lane & 15)) * PH
                   + ks * 32 + (lane >> 4) * 16);
#pragma unroll
        for (int nf = 0; nf < 8; nf++) {
            uint32_t bf[2];
            ldmB(bf, sS + (uint32_t)(wn * 64 + nf * 8 + (lane & 7)) * PH
                       + ks * 32 + ((lane >> 3) & 1) * 16);
            mma16816(acc[nf], af, bf);
        }
    }

    const int r = lane >> 2, cb = (lane & 3) * 2;
    const int b = bh >> 4, h = bh & 15;
#pragma unroll
    for (int nf = 0; nf < 8; nf++) {
        int d = wn * 64 + nf * 8 + cb;
        int i0 = wm * 16 + r;
        size_t base = ((size_t)(b * S_ + n * 64 + i0)) * H_ + h * 128 + d;
        float2 pv0 = *(const float2*)(o + base);
        float2 pv1 = *(const float2*)(o + base + 8 * H_);
        *(__half2*)(oh + base) = __floats2half2_rn(pv0.x + acc[nf][0], pv0.y + acc[nf][1]);
        *(__half2*)(oh + base + 8 * H_) = __floats2half2_rn(pv1.x + acc[nf][2], pv1.y + acc[nf][3]);
    }
}

// ---------------------------------------------------------------------------
// Launch
// ---------------------------------------------------------------------------
extern "C" void kernel_launch(void* const* d_in, const int* in_sizes, int n_in,
                              void* d_out, int out_size)
{
    (void)in_sizes; (void)n_in; (void)out_size;
    const float* x  = (const float*)d_in[0];
    const float* Wq = (const float*)d_in[1];
    const float* Wk = (const float*)d_in[2];
    const float* Wv = (const float*)d_in[3];
    const float* Wb = (const float*)d_in[4];
    const float* Wo = (const float*)d_in[5];
    float* out = (float*)d_out;
    float* out_state = out + (size_t)M_ * H_;

    float *po, *pP;
    __half *pqh, *pkh, *puh, *pvh, *pbb, *pSh, *pxh, *poh, *pWth;
    cudaGetSymbolAddress((void**)&pqh, g_qh);
    cudaGetSymbolAddress((void**)&pkh, g_kh);
    cudaGetSymbolAddress((void**)&puh, g_uh);
    cudaGetSymbolAddress((void**)&pvh, g_vh);
    cudaGetSymbolAddress((void**)&pbb, g_bb);
    cudaGetSymbolAddress((void**)&po,  g_o);
    cudaGetSymbolAddress((void**)&pP,  g_P);
    cudaGetSymbolAddress((void**)&pSh, g_Sh);
    cudaGetSymbolAddress((void**)&pxh, g_xh);
    cudaGetSymbolAddress((void**)&poh, g_oh);
    cudaGetSymbolAddress((void**)&pWth, g_Wth);

    cudaFuncSetAttribute(tcgemm_proj, cudaFuncAttributeMaxDynamicSharedMemorySize, GEMM_SMEM);
    cudaFuncSetAttribute(tcgemm_out,  cudaFuncAttributeMaxDynamicSharedMemorySize, GEMM_SMEM);
    cudaFuncSetAttribute(chunk_local, cudaFuncAttributeMaxDynamicSharedMemorySize, CL_SMEM);
    cudaFuncSetAttribute(inter_chunk, cudaFuncAttributeMaxDynamicSharedMemorySize, IN_SMEM);

    const size_t WSZ = (size_t)H_ * H_;

    dim3 tg(H_ / 32, H_ / 32, 5), tb(32, 8);
    transpose5<<<tg, tb>>>(Wq, Wk, Wv, Wb, Wo, pWth);

    convert_half<<<(M_ * (H_ / 4)) / 256, 256>>>(x, pxh);

    dim3 gp(H_ / 128, M_ / 128, 4);
    tcgemm_proj<<<gp, 256, GEMM_SMEM>>>(pxh, pWth, pqh, pkh, pvh, pbb);

    ewise_u<<<(M_ * (H_ / 8)) / 256, 256>>>(pvh, pbb, puh);

    dim3 gc(NC_, B_ * NH_);
    chunk_local<<<gc, 256, CL_SMEM>>>(pqh, pkh, puh, po, pP);
    prefix_state<<<B_ * NH_ * 8, 256>>>(pP, pSh, out_state);
    inter_chunk<<<gc, 256, IN_SMEM>>>(pqh, pSh, po, poh);

    dim3 go(H_ / 128, M_ / 128);
    tcgemm_out<<<go, 256, GEMM_SMEM>>>(poh, pWth + 4 * WSZ, out);
}